// round 1
// baseline (speedup 1.0000x reference)
#include <cuda_runtime.h>
#include <math_constants.h>

#define T_DIM 2048
#define B_DIM 2
#define E_DIM 1024
#define H_DIM 16
#define D_DIM 64
#define NHEADS (B_DIM * H_DIM)          // 32
#define NROWS  (T_DIM * B_DIM)          // 4096

// Scratch (device globals: allowed; no runtime allocation)
__device__ float g_Qh[NHEADS * T_DIM * D_DIM];   // (B*H, T, 64), scaling folded in
__device__ float g_Kh[NHEADS * T_DIM * D_DIM];
__device__ float g_Vh[NHEADS * T_DIM * D_DIM];
__device__ float g_ctx[NROWS * E_DIM];           // (T, B, E)

// ---------------------------------------------------------------------------
// C = (A @ W^T + bias) * scale
// A: [M=4096, K=1024] row-major (rows are (t,b) of a (T,B,E) tensor)
// W: [N=1024, K=1024] row-major
// headLayout=1: write C[m][n] to head tensor [(b*H + n/64), t, n%64]
// Block tile 64x64, 256 threads, 4x4 per thread, K-tile 16.
// ---------------------------------------------------------------------------
__global__ __launch_bounds__(256) void gemm_nt(const float* __restrict__ A,
                                               const float* __restrict__ W,
                                               const float* __restrict__ bias,
                                               float* __restrict__ C,
                                               float scale, int headLayout)
{
    __shared__ float As[16 * 68];   // As[k][m], stride 68 (16B-aligned float4 rows)
    __shared__ float Ws[16 * 68];   // Ws[k][n]

    const int tid = threadIdx.x;
    const int tx = tid & 15;            // n-group
    const int ty = tid >> 4;            // m-group
    const int bm = blockIdx.y << 6;
    const int bn = blockIdx.x << 6;

    const int lrow = tid >> 2;          // 0..63
    const int lc4  = (tid & 3) << 2;    // 0,4,8,12

    const float* Ag = A + (size_t)(bm + lrow) * E_DIM + lc4;
    const float* Wg = W + (size_t)(bn + lrow) * E_DIM + lc4;

    float acc[4][4];
    #pragma unroll
    for (int i = 0; i < 4; i++)
        #pragma unroll
        for (int j = 0; j < 4; j++) acc[i][j] = 0.f;

    for (int k0 = 0; k0 < E_DIM; k0 += 16) {
        float4 av = *(const float4*)(Ag + k0);
        float4 wv = *(const float4*)(Wg + k0);
        __syncthreads();   // previous tile's compute reads done
        As[(lc4 + 0) * 68 + lrow] = av.x;
        As[(lc4 + 1) * 68 + lrow] = av.y;
        As[(lc4 + 2) * 68 + lrow] = av.z;
        As[(lc4 + 3) * 68 + lrow] = av.w;
        Ws[(lc4 + 0) * 68 + lrow] = wv.x;
        Ws[(lc4 + 1) * 68 + lrow] = wv.y;
        Ws[(lc4 + 2) * 68 + lrow] = wv.z;
        Ws[(lc4 + 3) * 68 + lrow] = wv.w;
        __syncthreads();

        #pragma unroll
        for (int k = 0; k < 16; k++) {
            float4 a4 = *(const float4*)(As + k * 68 + (ty << 2));
            float4 b4 = *(const float4*)(Ws + k * 68 + (tx << 2));
            float aa[4] = {a4.x, a4.y, a4.z, a4.w};
            float bb[4] = {b4.x, b4.y, b4.z, b4.w};
            #pragma unroll
            for (int i = 0; i < 4; i++)
                #pragma unroll
                for (int j = 0; j < 4; j++)
                    acc[i][j] = fmaf(aa[i], bb[j], acc[i][j]);
        }
    }

    const int nbase = bn + (tx << 2);
    float bvals[4];
    #pragma unroll
    for (int j = 0; j < 4; j++) bvals[j] = bias[nbase + j];

    #pragma unroll
    for (int i = 0; i < 4; i++) {
        const int m = bm + (ty << 2) + i;
        #pragma unroll
        for (int j = 0; j < 4; j++) {
            const int n = nbase + j;
            float v = (acc[i][j] + bvals[j]) * scale;
            if (headLayout) {
                const int t  = m >> 1;      // B_DIM == 2
                const int b  = m & 1;
                const int h  = n >> 6;
                const int dd = n & 63;
                C[(((size_t)b * H_DIM + h) * T_DIM + t) * D_DIM + dd] = v;
            } else {
                C[(size_t)m * E_DIM + n] = v;
            }
        }
    }
}

// ---------------------------------------------------------------------------
// Flash attention fp32: one block = (64 queries) x (one head)
// 8 warps, each warp owns 8 query rows. Online softmax over 32 key tiles of 64.
// ---------------------------------------------------------------------------
__global__ __launch_bounds__(256) void attn_fwd(const float* __restrict__ Qh,
                                                const float* __restrict__ Kh,
                                                const float* __restrict__ Vh,
                                                float* __restrict__ ctx)
{
    extern __shared__ float sm[];
    float* Qs = sm;                  // 64*64, stride 64 (broadcast reads only)
    float* Ks = Qs + 64 * 64;        // 64 rows, stride 68 -> conflict-free LDS.128
    float* Vs = Ks + 64 * 68;        // 64*64, stride 64 (contiguous float2 reads)
    float* Ps = Vs + 64 * 64;        // 8 warps * 64 probs

    const int tid  = threadIdx.x;
    const int lane = tid & 31;
    const int w    = tid >> 5;
    const int qt   = blockIdx.x;     // query tile
    const int g    = blockIdx.y;     // head index b*H + h

    // Load Q tile (scaling already folded in by projection)
    const float* Qg = Qh + ((size_t)g * T_DIM + qt * 64) * D_DIM;
    #pragma unroll
    for (int it = 0; it < 4; it++) {
        int c   = tid + it * 256;           // 0..1023 float4 chunks
        int row = c >> 4;
        int c4  = (c & 15) << 2;
        *(float4*)(Qs + row * 64 + c4) = *(const float4*)(Qg + row * 64 + c4);
    }

    float m[8], l[8], accX[8], accY[8];
    #pragma unroll
    for (int r = 0; r < 8; r++) { m[r] = -CUDART_INF_F; l[r] = 0.f; accX[r] = 0.f; accY[r] = 0.f; }

    const float* Kg = Kh + (size_t)g * T_DIM * D_DIM;
    const float* Vg = Vh + (size_t)g * T_DIM * D_DIM;

    for (int st = 0; st < T_DIM / 64; st++) {
        __syncthreads();   // prior tile compute done (also covers Q load on st=0)
        #pragma unroll
        for (int it = 0; it < 4; it++) {
            int c   = tid + it * 256;
            int row = c >> 4;
            int c4  = (c & 15) << 2;
            *(float4*)(Ks + row * 68 + c4) = *(const float4*)(Kg + (size_t)(st * 64 + row) * 64 + c4);
            *(float4*)(Vs + row * 64 + c4) = *(const float4*)(Vg + (size_t)(st * 64 + row) * 64 + c4);
        }
        __syncthreads();

        #pragma unroll
        for (int r = 0; r < 8; r++) {
            const int row = w * 8 + r;
            const float4* qv = (const float4*)(Qs + row * 64);
            const float4* k0 = (const float4*)(Ks + lane * 68);
            const float4* k1 = (const float4*)(Ks + (lane + 32) * 68);
            float s0 = 0.f, s1 = 0.f;
            #pragma unroll
            for (int dq = 0; dq < 16; dq++) {
                float4 q = qv[dq];
                float4 a = k0[dq];
                float4 b = k1[dq];
                s0 = fmaf(q.x, a.x, fmaf(q.y, a.y, fmaf(q.z, a.z, fmaf(q.w, a.w, s0))));
                s1 = fmaf(q.x, b.x, fmaf(q.y, b.y, fmaf(q.z, b.z, fmaf(q.w, b.w, s1))));
            }
            // warp-wide softmax stats (64 keys live in this warp: 2/lane)
            float mt = fmaxf(s0, s1);
            #pragma unroll
            for (int off = 16; off; off >>= 1)
                mt = fmaxf(mt, __shfl_xor_sync(0xffffffffu, mt, off));
            float mnew  = fmaxf(m[r], mt);
            float alpha = __expf(m[r] - mnew);     // first tile: exp(-inf)=0
            float p0 = __expf(s0 - mnew);
            float p1 = __expf(s1 - mnew);
            float ps = p0 + p1;
            #pragma unroll
            for (int off = 16; off; off >>= 1)
                ps += __shfl_xor_sync(0xffffffffu, ps, off);
            m[r] = mnew;
            l[r] = l[r] * alpha + ps;

            Ps[w * 64 + lane]      = p0;
            Ps[w * 64 + lane + 32] = p1;
            __syncwarp();

            float ax = accX[r] * alpha;
            float ay = accY[r] * alpha;
            const float4* pp = (const float4*)(Ps + w * 64);
            #pragma unroll
            for (int j4 = 0; j4 < 16; j4++) {
                float4 p = pp[j4];
                const float* vb = Vs + (j4 * 4) * 64 + lane * 2;
                float2 v0 = *(const float2*)(vb);
                float2 v1 = *(const float2*)(vb + 64);
                float2 v2 = *(const float2*)(vb + 128);
                float2 v3 = *(const float2*)(vb + 192);
                ax = fmaf(p.x, v0.x, fmaf(p.y, v1.x, fmaf(p.z, v2.x, fmaf(p.w, v3.x, ax))));
                ay = fmaf(p.x, v0.y, fmaf(p.y, v1.y, fmaf(p.z, v2.y, fmaf(p.w, v3.y, ay))));
            }
            accX[r] = ax; accY[r] = ay;
            __syncwarp();   // Ps reads done before next row overwrites
        }
    }

    const int b = g >> 4;   // H_DIM == 16
    const int h = g & 15;
    #pragma unroll
    for (int r = 0; r < 8; r++) {
        const int row = w * 8 + r;
        const int t   = qt * 64 + row;
        const float inv = 1.f / l[r];
        float2 o = make_float2(accX[r] * inv, accY[r] * inv);
        *(float2*)(ctx + ((size_t)t * B_DIM + b) * E_DIM + h * 64 + lane * 2) = o;
    }
}

// ---------------------------------------------------------------------------
extern "C" void kernel_launch(void* const* d_in, const int* in_sizes, int n_in,
                              void* d_out, int out_size)
{
    const float* query = (const float*)d_in[0];
    const float* key   = (const float*)d_in[1];
    const float* value = (const float*)d_in[2];
    const float* Win   = (const float*)d_in[3];   // (3E, E)
    const float* bin   = (const float*)d_in[4];   // (3E,)
    const float* Wout  = (const float*)d_in[5];   // (E, E)
    const float* bout  = (const float*)d_in[6];   // (E,)
    float* out = (float*)d_out;

    float *Qh, *Kh, *Vh, *ctx;
    cudaGetSymbolAddress((void**)&Qh,  g_Qh);
    cudaGetSymbolAddress((void**)&Kh,  g_Kh);
    cudaGetSymbolAddress((void**)&Vh,  g_Vh);
    cudaGetSymbolAddress((void**)&ctx, g_ctx);

    dim3 ggrid(E_DIM / 64, NROWS / 64);   // (16, 64)
    const float scaling = 0.125f;          // 1/sqrt(64)

    gemm_nt<<<ggrid, 256>>>(query, Win,                     bin,             Qh,  scaling, 1);
    gemm_nt<<<ggrid, 256>>>(key,   Win + E_DIM * E_DIM,     bin + E_DIM,     Kh,  1.f,     1);
    gemm_nt<<<ggrid, 256>>>(value, Win + 2 * E_DIM * E_DIM, bin + 2 * E_DIM, Vh,  1.f,     1);

    const int smem = (64 * 64 + 64 * 68 + 64 * 64 + 8 * 64) * (int)sizeof(float); // 52224
    cudaFuncSetAttribute(attn_fwd, cudaFuncAttributeMaxDynamicSharedMemorySize, smem);
    attn_fwd<<<dim3(T_DIM / 64, NHEADS), 256, smem>>>(Qh, Kh, Vh, ctx);

    gemm_nt<<<ggrid, 256>>>(ctx, Wout, bout, out, 1.f, 0);
}

// round 3
// speedup vs baseline: 1.1957x; 1.1957x over previous
#include <cuda_runtime.h>
#include <cuda_bf16.h>
#include <math_constants.h>
#include <cstdint>

#define T_DIM 2048
#define B_DIM 2
#define E_DIM 1024
#define H_DIM 16
#define D_DIM 64
#define NHEADS (B_DIM * H_DIM)          // 32
#define NROWS  (T_DIM * B_DIM)          // 4096

// Scratch (device globals: allowed; no runtime allocation)
__device__ float g_Qh[NHEADS * T_DIM * D_DIM];   // (B*H, T, 64), scaling folded in
__device__ float g_Kh[NHEADS * T_DIM * D_DIM];
__device__ float g_Vh[NHEADS * T_DIM * D_DIM];
__device__ float g_ctx[NROWS * E_DIM];           // (T, B, E)

// ---------------------------------------------------------------------------
// MMA helpers (warp-level HMMA, bf16 inputs, fp32 accum)
// ---------------------------------------------------------------------------
__device__ __forceinline__ void ldsm4(uint32_t* r, uint32_t addr) {
    asm volatile("ldmatrix.sync.aligned.m8n8.x4.shared.b16 {%0,%1,%2,%3}, [%4];"
                 : "=r"(r[0]), "=r"(r[1]), "=r"(r[2]), "=r"(r[3]) : "r"(addr));
}

__device__ __forceinline__ void mma_bf16(float* d, const uint32_t* a,
                                         uint32_t b0, uint32_t b1) {
    asm volatile("mma.sync.aligned.m16n8k16.row.col.f32.bf16.bf16.f32 "
                 "{%0,%1,%2,%3}, {%4,%5,%6,%7}, {%8,%9}, {%0,%1,%2,%3};"
                 : "+f"(d[0]), "+f"(d[1]), "+f"(d[2]), "+f"(d[3])
                 : "r"(a[0]), "r"(a[1]), "r"(a[2]), "r"(a[3]), "r"(b0), "r"(b1));
}

__device__ __forceinline__ uint32_t smem_u32(const void* p) {
    return (uint32_t)__cvta_generic_to_shared(p);
}

__device__ __forceinline__ uint32_t pack_bf16(__nv_bfloat16 x, __nv_bfloat16 y) {
    __nv_bfloat162 v = __halves2bfloat162(x, y);
    return *reinterpret_cast<uint32_t*>(&v);
}

// ---------------------------------------------------------------------------
// C = (A @ W^T + bias) * scale   via bf16x3 split (hi/lo) tensor-core GEMM
// A: [4096, 1024] row-major, W: [1024, 1024] row-major
// Block tile 128x128, K-tile 32, 256 threads = 8 warps in 2(M) x 4(N).
// smem tiles stored with stride 40 bf16 (80B) rows -> conflict-free LDSM.
// headLayout=1: C[m][n] -> [(b*H + n/64), t, n%64] head tensor.
// ---------------------------------------------------------------------------
__global__ __launch_bounds__(256) void gemm_mma(const float* __restrict__ A,
                                                const float* __restrict__ W,
                                                const float* __restrict__ bias,
                                                float* __restrict__ C,
                                                float scale, int headLayout)
{
    __shared__ __align__(16) __nv_bfloat16 Ah[128 * 40];
    __shared__ __align__(16) __nv_bfloat16 Al[128 * 40];
    __shared__ __align__(16) __nv_bfloat16 Bh[128 * 40];
    __shared__ __align__(16) __nv_bfloat16 Bl[128 * 40];

    const int tid  = threadIdx.x;
    const int lane = tid & 31;
    const int wid  = tid >> 5;
    const int wm   = wid >> 2;      // 0..1  (M warp tile of 64)
    const int wn   = wid & 3;       // 0..3  (N warp tile of 32)
    const int bm   = blockIdx.y << 7;
    const int bn   = blockIdx.x << 7;

    // ldmatrix per-lane row addressing within a 16x16 bf16 block
    const int lrow  = lane & 15;
    const int lkoff = ((lane >> 4) & 1) << 4;   // 0 or 16 bytes

    const uint32_t sAh = smem_u32(Ah);
    const uint32_t sAl = smem_u32(Al);
    const uint32_t sBh = smem_u32(Bh);
    const uint32_t sBl = smem_u32(Bl);

    float acc[4][4][4];
    #pragma unroll
    for (int i = 0; i < 4; i++)
        #pragma unroll
        for (int j = 0; j < 4; j++)
            #pragma unroll
            for (int r = 0; r < 4; r++) acc[i][j][r] = 0.f;

    // Global load pattern: 4 chunks each for A and W; tile is 128 rows x 32 cols
    int arow[4], ac4[4];
    #pragma unroll
    for (int it = 0; it < 4; it++) {
        int chunk = tid + it * 256;       // 0..1023
        arow[it] = chunk >> 3;            // 0..127
        ac4[it]  = (chunk & 7) << 2;      // 0,4,...,28
    }

    for (int kt = 0; kt < E_DIM; kt += 32) {
        float4 apre[4], bpre[4];
        #pragma unroll
        for (int it = 0; it < 4; it++) {
            apre[it] = *(const float4*)(A + (size_t)(bm + arow[it]) * E_DIM + kt + ac4[it]);
            bpre[it] = *(const float4*)(W + (size_t)(bn + arow[it]) * E_DIM + kt + ac4[it]);
        }
        __syncthreads();   // previous tile compute done
        #pragma unroll
        for (int it = 0; it < 4; it++) {
            const int off = arow[it] * 40 + ac4[it];
            float v[4] = {apre[it].x, apre[it].y, apre[it].z, apre[it].w};
            __nv_bfloat16 h[4], l[4];
            #pragma unroll
            for (int j = 0; j < 4; j++) {
                h[j] = __float2bfloat16(v[j]);
                l[j] = __float2bfloat16(v[j] - __bfloat162float(h[j]));
            }
            *reinterpret_cast<uint32_t*>(&Ah[off])     = pack_bf16(h[0], h[1]);
            *reinterpret_cast<uint32_t*>(&Ah[off + 2]) = pack_bf16(h[2], h[3]);
            *reinterpret_cast<uint32_t*>(&Al[off])     = pack_bf16(l[0], l[1]);
            *reinterpret_cast<uint32_t*>(&Al[off + 2]) = pack_bf16(l[2], l[3]);

            float w4[4] = {bpre[it].x, bpre[it].y, bpre[it].z, bpre[it].w};
            #pragma unroll
            for (int j = 0; j < 4; j++) {
                h[j] = __float2bfloat16(w4[j]);
                l[j] = __float2bfloat16(w4[j] - __bfloat162float(h[j]));
            }
            *reinterpret_cast<uint32_t*>(&Bh[off])     = pack_bf16(h[0], h[1]);
            *reinterpret_cast<uint32_t*>(&Bh[off + 2]) = pack_bf16(h[2], h[3]);
            *reinterpret_cast<uint32_t*>(&Bl[off])     = pack_bf16(l[0], l[1]);
            *reinterpret_cast<uint32_t*>(&Bl[off + 2]) = pack_bf16(l[2], l[3]);
        }
        __syncthreads();

        #pragma unroll
        for (int ks = 0; ks < 2; ks++) {
            const int kbyte = ks * 32 + lkoff;
            uint32_t Afh[4][4], Afl[4][4];
            #pragma unroll
            for (int mt = 0; mt < 4; mt++) {
                const uint32_t row = (uint32_t)(wm * 64 + mt * 16 + lrow) * 80 + kbyte;
                ldsm4(Afh[mt], sAh + row);
                ldsm4(Afl[mt], sAl + row);
            }
            uint32_t Bfh[2][4], Bfl[2][4];
            #pragma unroll
            for (int p = 0; p < 2; p++) {
                const uint32_t row = (uint32_t)(wn * 32 + p * 16 + lrow) * 80 + kbyte;
                ldsm4(Bfh[p], sBh + row);
                ldsm4(Bfl[p], sBl + row);
            }
            #pragma unroll
            for (int mt = 0; mt < 4; mt++) {
                #pragma unroll
                for (int nt = 0; nt < 4; nt++) {
                    const int p = nt >> 1, s = nt & 1;
                    const uint32_t b0h = Bfh[p][s ? 1 : 0], b1h = Bfh[p][s ? 3 : 2];
                    const uint32_t b0l = Bfl[p][s ? 1 : 0], b1l = Bfl[p][s ? 3 : 2];
                    mma_bf16(acc[mt][nt], Afh[mt], b0h, b1h);   // hi*hi
                    mma_bf16(acc[mt][nt], Afh[mt], b0l, b1l);   // hi*lo
                    mma_bf16(acc[mt][nt], Afl[mt], b0h, b1h);   // lo*hi
                }
            }
        }
    }

    // Epilogue: c0=(g, 2t), c1=(g, 2t+1), c2=(g+8, 2t), c3=(g+8, 2t+1)
    const int g   = lane >> 2;
    const int tig = lane & 3;
    #pragma unroll
    for (int mt = 0; mt < 4; mt++) {
        #pragma unroll
        for (int nt = 0; nt < 4; nt++) {
            const int m0 = bm + wm * 64 + mt * 16 + g;
            const int n0 = bn + wn * 32 + nt * 8 + tig * 2;
            const float b0 = bias[n0], b1 = bias[n0 + 1];
            #pragma unroll
            for (int r = 0; r < 4; r++) {
                const int m = m0 + ((r >> 1) << 3);
                const int n = n0 + (r & 1);
                float v = (acc[mt][nt][r] + ((r & 1) ? b1 : b0)) * scale;
                if (headLayout) {
                    const int t  = m >> 1;       // B_DIM == 2
                    const int b  = m & 1;
                    const int h  = n >> 6;
                    const int dd = n & 63;
                    C[(((size_t)b * H_DIM + h) * T_DIM + t) * D_DIM + dd] = v;
                } else {
                    C[(size_t)m * E_DIM + n] = v;
                }
            }
        }
    }
}

// ---------------------------------------------------------------------------
// Flash attention fp32 (round-1 known-good version)
// ---------------------------------------------------------------------------
__global__ __launch_bounds__(256) void attn_fwd(const float* __restrict__ Qh,
                                                const float* __restrict__ Kh,
                                                const float* __restrict__ Vh,
                                                float* __restrict__ ctx)
{
    extern __shared__ float smbuf[];
    float* Qs = smbuf;               // 64*64
    float* Ks = Qs + 64 * 64;        // stride 68
    float* Vs = Ks + 64 * 68;        // 64*64
    float* Ps = Vs + 64 * 64;        // 8 warps * 64

    const int tid  = threadIdx.x;
    const int lane = tid & 31;
    const int w    = tid >> 5;
    const int qt   = blockIdx.x;
    const int g    = blockIdx.y;

    const float* Qg = Qh + ((size_t)g * T_DIM + qt * 64) * D_DIM;
    #pragma unroll
    for (int it = 0; it < 4; it++) {
        int c   = tid + it * 256;
        int row = c >> 4;
        int c4  = (c & 15) << 2;
        *(float4*)(Qs + row * 64 + c4) = *(const float4*)(Qg + row * 64 + c4);
    }

    float m[8], l[8], accX[8], accY[8];
    #pragma unroll
    for (int r = 0; r < 8; r++) { m[r] = -CUDART_INF_F; l[r] = 0.f; accX[r] = 0.f; accY[r] = 0.f; }

    const float* Kg = Kh + (size_t)g * T_DIM * D_DIM;
    const float* Vg = Vh + (size_t)g * T_DIM * D_DIM;

    for (int st = 0; st < T_DIM / 64; st++) {
        __syncthreads();
        #pragma unroll
        for (int it = 0; it < 4; it++) {
            int c   = tid + it * 256;
            int row = c >> 4;
            int c4  = (c & 15) << 2;
            *(float4*)(Ks + row * 68 + c4) = *(const float4*)(Kg + (size_t)(st * 64 + row) * 64 + c4);
            *(float4*)(Vs + row * 64 + c4) = *(const float4*)(Vg + (size_t)(st * 64 + row) * 64 + c4);
        }
        __syncthreads();

        #pragma unroll
        for (int r = 0; r < 8; r++) {
            const int row = w * 8 + r;
            const float4* qv = (const float4*)(Qs + row * 64);
            const float4* k0 = (const float4*)(Ks + lane * 68);
            const float4* k1 = (const float4*)(Ks + (lane + 32) * 68);
            float s0 = 0.f, s1 = 0.f;
            #pragma unroll
            for (int dq = 0; dq < 16; dq++) {
                float4 q = qv[dq];
                float4 a = k0[dq];
                float4 b = k1[dq];
                s0 = fmaf(q.x, a.x, fmaf(q.y, a.y, fmaf(q.z, a.z, fmaf(q.w, a.w, s0))));
                s1 = fmaf(q.x, b.x, fmaf(q.y, b.y, fmaf(q.z, b.z, fmaf(q.w, b.w, s1))));
            }
            float mt = fmaxf(s0, s1);
            #pragma unroll
            for (int off = 16; off; off >>= 1)
                mt = fmaxf(mt, __shfl_xor_sync(0xffffffffu, mt, off));
            float mnew  = fmaxf(m[r], mt);
            float alpha = __expf(m[r] - mnew);
            float p0 = __expf(s0 - mnew);
            float p1 = __expf(s1 - mnew);
            float ps = p0 + p1;
            #pragma unroll
            for (int off = 16; off; off >>= 1)
                ps += __shfl_xor_sync(0xffffffffu, ps, off);
            m[r] = mnew;
            l[r] = l[r] * alpha + ps;

            Ps[w * 64 + lane]      = p0;
            Ps[w * 64 + lane + 32] = p1;
            __syncwarp();

            float ax = accX[r] * alpha;
            float ay = accY[r] * alpha;
            const float4* pp = (const float4*)(Ps + w * 64);
            #pragma unroll
            for (int j4 = 0; j4 < 16; j4++) {
                float4 p = pp[j4];
                const float* vb = Vs + (j4 * 4) * 64 + lane * 2;
                float2 v0 = *(const float2*)(vb);
                float2 v1 = *(const float2*)(vb + 64);
                float2 v2 = *(const float2*)(vb + 128);
                float2 v3 = *(const float2*)(vb + 192);
                ax = fmaf(p.x, v0.x, fmaf(p.y, v1.x, fmaf(p.z, v2.x, fmaf(p.w, v3.x, ax))));
                ay = fmaf(p.x, v0.y, fmaf(p.y, v1.y, fmaf(p.z, v2.y, fmaf(p.w, v3.y, ay))));
            }
            accX[r] = ax; accY[r] = ay;
            __syncwarp();
        }
    }

    const int b = g >> 4;
    const int h = g & 15;
    #pragma unroll
    for (int r = 0; r < 8; r++) {
        const int row = w * 8 + r;
        const int t   = qt * 64 + row;
        const float inv = 1.f / l[r];
        float2 o = make_float2(accX[r] * inv, accY[r] * inv);
        *(float2*)(ctx + ((size_t)t * B_DIM + b) * E_DIM + h * 64 + lane * 2) = o;
    }
}

// ---------------------------------------------------------------------------
extern "C" void kernel_launch(void* const* d_in, const int* in_sizes, int n_in,
                              void* d_out, int out_size)
{
    const float* query = (const float*)d_in[0];
    const float* key   = (const float*)d_in[1];
    const float* value = (const float*)d_in[2];
    const float* Win   = (const float*)d_in[3];   // (3E, E)
    const float* bin   = (const float*)d_in[4];   // (3E,)
    const float* Wout  = (const float*)d_in[5];   // (E, E)
    const float* bout  = (const float*)d_in[6];   // (E,)
    float* out = (float*)d_out;

    float *Qh, *Kh, *Vh, *ctx;
    cudaGetSymbolAddress((void**)&Qh,  g_Qh);
    cudaGetSymbolAddress((void**)&Kh,  g_Kh);
    cudaGetSymbolAddress((void**)&Vh,  g_Vh);
    cudaGetSymbolAddress((void**)&ctx, g_ctx);

    dim3 ggrid(E_DIM / 128, NROWS / 128);   // (8, 32)
    const float scaling = 0.125f;            // 1/sqrt(64)

    gemm_mma<<<ggrid, 256>>>(query, Win,                     bin,             Qh,  scaling, 1);
    gemm_mma<<<ggrid, 256>>>(key,   Win + E_DIM * E_DIM,     bin + E_DIM,     Kh,  1.f,     1);
    gemm_mma<<<ggrid, 256>>>(value, Win + 2 * E_DIM * E_DIM, bin + 2 * E_DIM, Vh,  1.f,     1);

    const int smem = (64 * 64 + 64 * 68 + 64 * 64 + 8 * 64) * (int)sizeof(float); // 52224
    cudaFuncSetAttribute(attn_fwd, cudaFuncAttributeMaxDynamicSharedMemorySize, smem);
    attn_fwd<<<dim3(T_DIM / 64, NHEADS), 256, smem>>>(Qh, Kh, Vh, ctx);

    gemm_mma<<<ggrid, 256>>>(ctx, Wout, bout, out, 1.f, 0);
}

// round 4
// speedup vs baseline: 4.1054x; 3.4335x over previous
#include <cuda_runtime.h>
#include <cuda_bf16.h>
#include <math_constants.h>
#include <cstdint>

#define T_DIM 2048
#define B_DIM 2
#define E_DIM 1024
#define H_DIM 16
#define D_DIM 64
#define NHEADS (B_DIM * H_DIM)          // 32
#define NROWS  (T_DIM * B_DIM)          // 4096

// Scratch (device globals; no runtime allocation)
__device__ __nv_bfloat16 g_Qhb[NHEADS * T_DIM * D_DIM];
__device__ __nv_bfloat16 g_Qlb[NHEADS * T_DIM * D_DIM];
__device__ __nv_bfloat16 g_Khb[NHEADS * T_DIM * D_DIM];
__device__ __nv_bfloat16 g_Klb[NHEADS * T_DIM * D_DIM];
__device__ __nv_bfloat16 g_Vhb[NHEADS * T_DIM * D_DIM];
__device__ __nv_bfloat16 g_Vlb[NHEADS * T_DIM * D_DIM];
__device__ float g_ctx[NROWS * E_DIM];           // (T, B, E)

// ---------------------------------------------------------------------------
// MMA helpers
// ---------------------------------------------------------------------------
__device__ __forceinline__ void ldsm4(uint32_t* r, uint32_t addr) {
    asm volatile("ldmatrix.sync.aligned.m8n8.x4.shared.b16 {%0,%1,%2,%3}, [%4];"
                 : "=r"(r[0]), "=r"(r[1]), "=r"(r[2]), "=r"(r[3]) : "r"(addr));
}
__device__ __forceinline__ void ldsm4t(uint32_t* r, uint32_t addr) {
    asm volatile("ldmatrix.sync.aligned.m8n8.x4.trans.shared.b16 {%0,%1,%2,%3}, [%4];"
                 : "=r"(r[0]), "=r"(r[1]), "=r"(r[2]), "=r"(r[3]) : "r"(addr));
}
__device__ __forceinline__ void mma_bf16(float* d, const uint32_t* a,
                                         uint32_t b0, uint32_t b1) {
    asm volatile("mma.sync.aligned.m16n8k16.row.col.f32.bf16.bf16.f32 "
                 "{%0,%1,%2,%3}, {%4,%5,%6,%7}, {%8,%9}, {%0,%1,%2,%3};"
                 : "+f"(d[0]), "+f"(d[1]), "+f"(d[2]), "+f"(d[3])
                 : "r"(a[0]), "r"(a[1]), "r"(a[2]), "r"(a[3]), "r"(b0), "r"(b1));
}
__device__ __forceinline__ uint32_t smem_u32(const void* p) {
    return (uint32_t)__cvta_generic_to_shared(p);
}
__device__ __forceinline__ uint32_t pack_bf16(__nv_bfloat16 x, __nv_bfloat16 y) {
    __nv_bfloat162 v = __halves2bfloat162(x, y);
    return *reinterpret_cast<uint32_t*>(&v);
}
// split pair of fp32 into packed bf16 hi and lo words
__device__ __forceinline__ void split2(float a, float b, uint32_t& hi, uint32_t& lo) {
    __nv_bfloat16 ha = __float2bfloat16(a), hb = __float2bfloat16(b);
    hi = pack_bf16(ha, hb);
    lo = pack_bf16(__float2bfloat16(a - __bfloat162float(ha)),
                   __float2bfloat16(b - __bfloat162float(hb)));
}

// ---------------------------------------------------------------------------
// C = (A @ W^T + bias) * scale   via bf16x3 split tensor-core GEMM
// mode 0: fp32 C, (T*B, E) layout.  mode 1: bf16 hi/lo split head tensors.
// ---------------------------------------------------------------------------
__global__ __launch_bounds__(256) void gemm_mma(const float* __restrict__ A,
                                                const float* __restrict__ W,
                                                const float* __restrict__ bias,
                                                float* __restrict__ C,
                                                __nv_bfloat16* __restrict__ Chb,
                                                __nv_bfloat16* __restrict__ Clb,
                                                float scale, int mode)
{
    __shared__ __align__(16) __nv_bfloat16 Ah[128 * 40];
    __shared__ __align__(16) __nv_bfloat16 Al[128 * 40];
    __shared__ __align__(16) __nv_bfloat16 Bh[128 * 40];
    __shared__ __align__(16) __nv_bfloat16 Bl[128 * 40];

    const int tid  = threadIdx.x;
    const int lane = tid & 31;
    const int wid  = tid >> 5;
    const int wm   = wid >> 2;
    const int wn   = wid & 3;
    const int bm   = blockIdx.y << 7;
    const int bn   = blockIdx.x << 7;

    const int lrow  = lane & 15;
    const int lkoff = ((lane >> 4) & 1) << 4;

    const uint32_t sAh = smem_u32(Ah);
    const uint32_t sAl = smem_u32(Al);
    const uint32_t sBh = smem_u32(Bh);
    const uint32_t sBl = smem_u32(Bl);

    float acc[4][4][4];
    #pragma unroll
    for (int i = 0; i < 4; i++)
        #pragma unroll
        for (int j = 0; j < 4; j++)
            #pragma unroll
            for (int r = 0; r < 4; r++) acc[i][j][r] = 0.f;

    int arow[4], ac4[4];
    #pragma unroll
    for (int it = 0; it < 4; it++) {
        int chunk = tid + it * 256;
        arow[it] = chunk >> 3;
        ac4[it]  = (chunk & 7) << 2;
    }

    for (int kt = 0; kt < E_DIM; kt += 32) {
        float4 apre[4], bpre[4];
        #pragma unroll
        for (int it = 0; it < 4; it++) {
            apre[it] = *(const float4*)(A + (size_t)(bm + arow[it]) * E_DIM + kt + ac4[it]);
            bpre[it] = *(const float4*)(W + (size_t)(bn + arow[it]) * E_DIM + kt + ac4[it]);
        }
        __syncthreads();
        #pragma unroll
        for (int it = 0; it < 4; it++) {
            const int off = arow[it] * 40 + ac4[it];
            uint32_t hi, lo;
            split2(apre[it].x, apre[it].y, hi, lo);
            *reinterpret_cast<uint32_t*>(&Ah[off]) = hi;
            *reinterpret_cast<uint32_t*>(&Al[off]) = lo;
            split2(apre[it].z, apre[it].w, hi, lo);
            *reinterpret_cast<uint32_t*>(&Ah[off + 2]) = hi;
            *reinterpret_cast<uint32_t*>(&Al[off + 2]) = lo;
            split2(bpre[it].x, bpre[it].y, hi, lo);
            *reinterpret_cast<uint32_t*>(&Bh[off]) = hi;
            *reinterpret_cast<uint32_t*>(&Bl[off]) = lo;
            split2(bpre[it].z, bpre[it].w, hi, lo);
            *reinterpret_cast<uint32_t*>(&Bh[off + 2]) = hi;
            *reinterpret_cast<uint32_t*>(&Bl[off + 2]) = lo;
        }
        __syncthreads();

        #pragma unroll
        for (int ks = 0; ks < 2; ks++) {
            const int kbyte = ks * 32 + lkoff;
            uint32_t Afh[4][4], Afl[4][4];
            #pragma unroll
            for (int mt = 0; mt < 4; mt++) {
                const uint32_t row = (uint32_t)(wm * 64 + mt * 16 + lrow) * 80 + kbyte;
                ldsm4(Afh[mt], sAh + row);
                ldsm4(Afl[mt], sAl + row);
            }
            uint32_t Bfh[2][4], Bfl[2][4];
            #pragma unroll
            for (int p = 0; p < 2; p++) {
                const uint32_t row = (uint32_t)(wn * 32 + p * 16 + lrow) * 80 + kbyte;
                ldsm4(Bfh[p], sBh + row);
                ldsm4(Bfl[p], sBl + row);
            }
            #pragma unroll
            for (int mt = 0; mt < 4; mt++) {
                #pragma unroll
                for (int nt = 0; nt < 4; nt++) {
                    const int p = nt >> 1, s = nt & 1;
                    const uint32_t b0h = Bfh[p][s ? 1 : 0], b1h = Bfh[p][s ? 3 : 2];
                    const uint32_t b0l = Bfl[p][s ? 1 : 0], b1l = Bfl[p][s ? 3 : 2];
                    mma_bf16(acc[mt][nt], Afh[mt], b0h, b1h);
                    mma_bf16(acc[mt][nt], Afh[mt], b0l, b1l);
                    mma_bf16(acc[mt][nt], Afl[mt], b0h, b1h);
                }
            }
        }
    }

    const int g   = lane >> 2;
    const int tig = lane & 3;
    #pragma unroll
    for (int mt = 0; mt < 4; mt++) {
        #pragma unroll
        for (int nt = 0; nt < 4; nt++) {
            const int m0 = bm + wm * 64 + mt * 16 + g;
            const int n0 = bn + wn * 32 + nt * 8 + tig * 2;
            const float b0 = bias[n0], b1 = bias[n0 + 1];
            float v[4];
            #pragma unroll
            for (int r = 0; r < 4; r++)
                v[r] = (acc[mt][nt][r] + ((r & 1) ? b1 : b0)) * scale;
            if (mode) {
                #pragma unroll
                for (int rr = 0; rr < 2; rr++) {
                    const int m = m0 + rr * 8;
                    const int t = m >> 1;        // B_DIM == 2
                    const int b = m & 1;
                    const int h = n0 >> 6;
                    const int dd = n0 & 63;
                    uint32_t hi, lo;
                    split2(v[rr * 2], v[rr * 2 + 1], hi, lo);
                    const size_t idx = (((size_t)(b * H_DIM + h)) * T_DIM + t) * D_DIM + dd;
                    *reinterpret_cast<uint32_t*>(&Chb[idx]) = hi;
                    *reinterpret_cast<uint32_t*>(&Clb[idx]) = lo;
                }
            } else {
                #pragma unroll
                for (int r = 0; r < 4; r++) {
                    const int m = m0 + ((r >> 1) << 3);
                    const int n = n0 + (r & 1);
                    C[(size_t)m * E_DIM + n] = v[r];
                }
            }
        }
    }
}

// ---------------------------------------------------------------------------
// MMA flash attention. Block = 128 queries x 1 head; 8 warps x 16 q-rows.
// Inputs are pre-split bf16 hi/lo head tensors (scaling folded into Q).
// ---------------------------------------------------------------------------
#define OFF_KH 0
#define OFF_KL 9216
#define OFF_VH 18432
#define OFF_VL 27648
#define OFF_QH 0
#define OFF_QL 18432

__global__ __launch_bounds__(256) void attn_mma(
    const __nv_bfloat16* __restrict__ Qhb, const __nv_bfloat16* __restrict__ Qlb,
    const __nv_bfloat16* __restrict__ Khb, const __nv_bfloat16* __restrict__ Klb,
    const __nv_bfloat16* __restrict__ Vhb, const __nv_bfloat16* __restrict__ Vlb,
    float* __restrict__ ctx)
{
    __shared__ __align__(16) char smraw[36864];

    const int tid  = threadIdx.x;
    const int lane = tid & 31;
    const int w    = tid >> 5;
    const int qt   = blockIdx.x;     // 0..15
    const int hg   = blockIdx.y;     // 0..31  = b*H + h
    const int lrow = lane & 15;
    const int lk16 = ((lane >> 4) & 1) << 4;
    const int rg   = lane >> 2;
    const int tig  = lane & 3;

    const uint32_t uSM = smem_u32(smraw);

    // ---- stage Q (128 rows x 64 bf16, 144B stride) and load fragments ----
    {
        const uint4* gqh = (const uint4*)(Qhb + ((size_t)hg * T_DIM + qt * 128) * D_DIM);
        const uint4* gql = (const uint4*)(Qlb + ((size_t)hg * T_DIM + qt * 128) * D_DIM);
        #pragma unroll
        for (int i = 0; i < 4; i++) {
            int c = tid + i * 256;          // 0..1023
            int row = c >> 3, j = c & 7;
            *(uint4*)(smraw + OFF_QH + row * 144 + j * 16) = gqh[c];
            *(uint4*)(smraw + OFF_QL + row * 144 + j * 16) = gql[c];
        }
    }
    __syncthreads();

    uint32_t QH[4][4], QL[4][4];
    {
        const uint32_t rb = (uint32_t)(w * 16 + lrow) * 144 + lk16;
        #pragma unroll
        for (int kb = 0; kb < 4; kb++) {
            ldsm4(QH[kb], uSM + OFF_QH + rb + kb * 32);
            ldsm4(QL[kb], uSM + OFF_QL + rb + kb * 32);
        }
    }

    float o[8][4];
    #pragma unroll
    for (int nt = 0; nt < 8; nt++)
        #pragma unroll
        for (int r = 0; r < 4; r++) o[nt][r] = 0.f;
    float m0 = -CUDART_INF_F, m1 = -CUDART_INF_F, l0 = 0.f, l1 = 0.f;

    const uint4* gKh = (const uint4*)(Khb + (size_t)hg * T_DIM * D_DIM);
    const uint4* gKl = (const uint4*)(Klb + (size_t)hg * T_DIM * D_DIM);
    const uint4* gVh = (const uint4*)(Vhb + (size_t)hg * T_DIM * D_DIM);
    const uint4* gVl = (const uint4*)(Vlb + (size_t)hg * T_DIM * D_DIM);

    for (int st = 0; st < T_DIM / 64; st++) {
        // prefetch 64x64 bf16 tile of each tensor (512 uint4 each)
        uint4 rkh[2], rkl[2], rvh[2], rvl[2];
        #pragma unroll
        for (int i = 0; i < 2; i++) {
            int c = st * 512 + tid + i * 256;
            rkh[i] = gKh[c]; rkl[i] = gKl[c]; rvh[i] = gVh[c]; rvl[i] = gVl[c];
        }
        __syncthreads();   // prior tile's smem reads done (also covers Q frag reads at st=0)
        #pragma unroll
        for (int i = 0; i < 2; i++) {
            int c = tid + i * 256;
            int row = c >> 3, j = c & 7;
            int off = row * 144 + j * 16;
            *(uint4*)(smraw + OFF_KH + off) = rkh[i];
            *(uint4*)(smraw + OFF_KL + off) = rkl[i];
            *(uint4*)(smraw + OFF_VH + off) = rvh[i];
            *(uint4*)(smraw + OFF_VL + off) = rvl[i];
        }
        __syncthreads();

        // ---- S = Q K^T (bf16x3), S tile 16(q-rows of warp) x 64(keys) ----
        float s[8][4];
        #pragma unroll
        for (int nt = 0; nt < 8; nt++)
            #pragma unroll
            for (int r = 0; r < 4; r++) s[nt][r] = 0.f;

        #pragma unroll
        for (int kb = 0; kb < 4; kb++) {
            uint32_t bh[4][4], bl[4][4];
            #pragma unroll
            for (int nb = 0; nb < 4; nb++) {
                const uint32_t a = uSM + OFF_KH + (uint32_t)(nb * 16 + lrow) * 144 + kb * 32 + lk16;
                ldsm4(bh[nb], a);
                ldsm4(bl[nb], a + (OFF_KL - OFF_KH));
            }
            #pragma unroll
            for (int nb = 0; nb < 4; nb++) {
                #pragma unroll
                for (int hs = 0; hs < 2; hs++) {
                    const int nt = nb * 2 + hs;
                    mma_bf16(s[nt], QH[kb], bh[nb][hs], bh[nb][hs + 2]);
                    mma_bf16(s[nt], QH[kb], bl[nb][hs], bl[nb][hs + 2]);
                    mma_bf16(s[nt], QL[kb], bh[nb][hs], bh[nb][hs + 2]);
                }
            }
        }

        // ---- online softmax (rows rg and rg+8 of this warp's 16) ----
        float mx0 = -CUDART_INF_F, mx1 = -CUDART_INF_F;
        #pragma unroll
        for (int nt = 0; nt < 8; nt++) {
            mx0 = fmaxf(mx0, fmaxf(s[nt][0], s[nt][1]));
            mx1 = fmaxf(mx1, fmaxf(s[nt][2], s[nt][3]));
        }
        mx0 = fmaxf(mx0, __shfl_xor_sync(0xffffffffu, mx0, 1));
        mx0 = fmaxf(mx0, __shfl_xor_sync(0xffffffffu, mx0, 2));
        mx1 = fmaxf(mx1, __shfl_xor_sync(0xffffffffu, mx1, 1));
        mx1 = fmaxf(mx1, __shfl_xor_sync(0xffffffffu, mx1, 2));
        const float mn0 = fmaxf(m0, mx0), mn1 = fmaxf(m1, mx1);
        const float al0 = __expf(m0 - mn0), al1 = __expf(m1 - mn1);
        m0 = mn0; m1 = mn1;
        float sum0 = 0.f, sum1 = 0.f;
        #pragma unroll
        for (int nt = 0; nt < 8; nt++) {
            s[nt][0] = __expf(s[nt][0] - m0);
            s[nt][1] = __expf(s[nt][1] - m0);
            s[nt][2] = __expf(s[nt][2] - m1);
            s[nt][3] = __expf(s[nt][3] - m1);
            sum0 += s[nt][0] + s[nt][1];
            sum1 += s[nt][2] + s[nt][3];
        }
        sum0 += __shfl_xor_sync(0xffffffffu, sum0, 1);
        sum0 += __shfl_xor_sync(0xffffffffu, sum0, 2);
        sum1 += __shfl_xor_sync(0xffffffffu, sum1, 1);
        sum1 += __shfl_xor_sync(0xffffffffu, sum1, 2);
        l0 = l0 * al0 + sum0;
        l1 = l1 * al1 + sum1;
        #pragma unroll
        for (int nt = 0; nt < 8; nt++) {
            o[nt][0] *= al0; o[nt][1] *= al0;
            o[nt][2] *= al1; o[nt][3] *= al1;
        }

        // ---- P accum -> A fragments (hi/lo), k-block kb covers S tiles 2kb,2kb+1
        uint32_t AH[4][4], AL[4][4];
        #pragma unroll
        for (int kb = 0; kb < 4; kb++) {
            const int t0 = 2 * kb, t1 = 2 * kb + 1;
            split2(s[t0][0], s[t0][1], AH[kb][0], AL[kb][0]);
            split2(s[t0][2], s[t0][3], AH[kb][1], AL[kb][1]);
            split2(s[t1][0], s[t1][1], AH[kb][2], AL[kb][2]);
            split2(s[t1][2], s[t1][3], AH[kb][3], AL[kb][3]);
        }

        // ---- O += P V  (trans ldmatrix: pairs (r0,r1) and (r2,r3)) ----
        #pragma unroll
        for (int kb = 0; kb < 4; kb++) {
            uint32_t vh[4][4], vl[4][4];
            #pragma unroll
            for (int db = 0; db < 4; db++) {
                const uint32_t a = uSM + OFF_VH + (uint32_t)(kb * 16 + lrow) * 144 + db * 32 + lk16;
                ldsm4t(vh[db], a);
                ldsm4t(vl[db], a + (OFF_VL - OFF_VH));
            }
            #pragma unroll
            for (int db = 0; db < 4; db++) {
                #pragma unroll
                for (int hs = 0; hs < 2; hs++) {
                    const int nt = db * 2 + hs;
                    const uint32_t b0h = vh[db][hs * 2], b1h = vh[db][hs * 2 + 1];
                    mma_bf16(o[nt], AH[kb], b0h, b1h);
                    mma_bf16(o[nt], AL[kb], b0h, b1h);
                    mma_bf16(o[nt], AH[kb], vl[db][hs * 2], vl[db][hs * 2 + 1]);
                }
            }
        }
    }

    // ---- epilogue: normalize and write ctx (T, B, E) ----
    const float inv0 = 1.f / l0, inv1 = 1.f / l1;
    const int bb = hg >> 4;      // H_DIM == 16
    const int hh = hg & 15;
    const int q0 = qt * 128 + w * 16 + rg;
    #pragma unroll
    for (int nt = 0; nt < 8; nt++) {
        const int d = hh * 64 + nt * 8 + tig * 2;
        *(float2*)(ctx + ((size_t)q0 * B_DIM + bb) * E_DIM + d) =
            make_float2(o[nt][0] * inv0, o[nt][1] * inv0);
        *(float2*)(ctx + ((size_t)(q0 + 8) * B_DIM + bb) * E_DIM + d) =
            make_float2(o[nt][2] * inv1, o[nt][3] * inv1);
    }
}

// ---------------------------------------------------------------------------
extern "C" void kernel_launch(void* const* d_in, const int* in_sizes, int n_in,
                              void* d_out, int out_size)
{
    const float* query = (const float*)d_in[0];
    const float* key   = (const float*)d_in[1];
    const float* value = (const float*)d_in[2];
    const float* Win   = (const float*)d_in[3];   // (3E, E)
    const float* bin   = (const float*)d_in[4];   // (3E,)
    const float* Wout  = (const float*)d_in[5];   // (E, E)
    const float* bout  = (const float*)d_in[6];   // (E,)
    float* out = (float*)d_out;

    __nv_bfloat16 *Qhb, *Qlb, *Khb, *Klb, *Vhb, *Vlb;
    float* ctx;
    cudaGetSymbolAddress((void**)&Qhb, g_Qhb);
    cudaGetSymbolAddress((void**)&Qlb, g_Qlb);
    cudaGetSymbolAddress((void**)&Khb, g_Khb);
    cudaGetSymbolAddress((void**)&Klb, g_Klb);
    cudaGetSymbolAddress((void**)&Vhb, g_Vhb);
    cudaGetSymbolAddress((void**)&Vlb, g_Vlb);
    cudaGetSymbolAddress((void**)&ctx, g_ctx);

    dim3 ggrid(E_DIM / 128, NROWS / 128);   // (8, 32)
    const float scaling = 0.125f;            // 1/sqrt(64)

    gemm_mma<<<ggrid, 256>>>(query, Win,                     bin,             nullptr, Qhb, Qlb, scaling, 1);
    gemm_mma<<<ggrid, 256>>>(key,   Win + E_DIM * E_DIM,     bin + E_DIM,     nullptr, Khb, Klb, 1.f,     1);
    gemm_mma<<<ggrid, 256>>>(value, Win + 2 * E_DIM * E_DIM, bin + 2 * E_DIM, nullptr, Vhb, Vlb, 1.f,     1);

    attn_mma<<<dim3(T_DIM / 128, NHEADS), 256>>>(Qhb, Qlb, Khb, Klb, Vhb, Vlb, ctx);

    gemm_mma<<<ggrid, 256>>>(ctx, Wout, bout, out, nullptr, nullptr, 1.f, 0);
}

// round 5
// speedup vs baseline: 5.3032x; 1.2918x over previous
#include <cuda_runtime.h>
#include <cuda_bf16.h>
#include <math_constants.h>
#include <cstdint>

#define T_DIM 2048
#define B_DIM 2
#define E_DIM 1024
#define H_DIM 16
#define D_DIM 64
#define NHEADS (B_DIM * H_DIM)          // 32
#define NROWS  (T_DIM * B_DIM)          // 4096

// Scratch (device globals; no runtime allocation)
__device__ float         g_Qtf[NHEADS * T_DIM * D_DIM];   // tf32-rounded, scale*log2e folded
__device__ float         g_Ktf[NHEADS * T_DIM * D_DIM];   // tf32-rounded
__device__ __nv_bfloat16 g_Vhb[NHEADS * T_DIM * D_DIM];
__device__ __nv_bfloat16 g_Vlb[NHEADS * T_DIM * D_DIM];
__device__ float         g_ctx[NROWS * E_DIM];            // (T, B, E)

// ---------------------------------------------------------------------------
// helpers
// ---------------------------------------------------------------------------
__device__ __forceinline__ void ldsm4(uint32_t* r, uint32_t addr) {
    asm volatile("ldmatrix.sync.aligned.m8n8.x4.shared.b16 {%0,%1,%2,%3}, [%4];"
                 : "=r"(r[0]), "=r"(r[1]), "=r"(r[2]), "=r"(r[3]) : "r"(addr));
}
__device__ __forceinline__ void ldsm4t(uint32_t* r, uint32_t addr) {
    asm volatile("ldmatrix.sync.aligned.m8n8.x4.trans.shared.b16 {%0,%1,%2,%3}, [%4];"
                 : "=r"(r[0]), "=r"(r[1]), "=r"(r[2]), "=r"(r[3]) : "r"(addr));
}
__device__ __forceinline__ void mma_bf16(float* d, const uint32_t* a,
                                         uint32_t b0, uint32_t b1) {
    asm volatile("mma.sync.aligned.m16n8k16.row.col.f32.bf16.bf16.f32 "
                 "{%0,%1,%2,%3}, {%4,%5,%6,%7}, {%8,%9}, {%0,%1,%2,%3};"
                 : "+f"(d[0]), "+f"(d[1]), "+f"(d[2]), "+f"(d[3])
                 : "r"(a[0]), "r"(a[1]), "r"(a[2]), "r"(a[3]), "r"(b0), "r"(b1));
}
__device__ __forceinline__ void mma_tf32(float* d, const uint32_t* a,
                                         uint32_t b0, uint32_t b1) {
    asm volatile("mma.sync.aligned.m16n8k8.row.col.f32.tf32.tf32.f32 "
                 "{%0,%1,%2,%3}, {%4,%5,%6,%7}, {%8,%9}, {%0,%1,%2,%3};"
                 : "+f"(d[0]), "+f"(d[1]), "+f"(d[2]), "+f"(d[3])
                 : "r"(a[0]), "r"(a[1]), "r"(a[2]), "r"(a[3]), "r"(b0), "r"(b1));
}
__device__ __forceinline__ uint32_t smem_u32(const void* p) {
    return (uint32_t)__cvta_generic_to_shared(p);
}
__device__ __forceinline__ uint32_t pack_bf16(__nv_bfloat16 x, __nv_bfloat16 y) {
    __nv_bfloat162 v = __halves2bfloat162(x, y);
    return *reinterpret_cast<uint32_t*>(&v);
}
__device__ __forceinline__ void split2(float a, float b, uint32_t& hi, uint32_t& lo) {
    __nv_bfloat16 ha = __float2bfloat16(a), hb = __float2bfloat16(b);
    hi = pack_bf16(ha, hb);
    lo = pack_bf16(__float2bfloat16(a - __bfloat162float(ha)),
                   __float2bfloat16(b - __bfloat162float(hb)));
}
__device__ __forceinline__ float to_tf32(float x) {
    uint32_t r;
    asm("cvt.rna.tf32.f32 %0, %1;" : "=r"(r) : "f"(x));
    return __uint_as_float(r);
}
__device__ __forceinline__ float ex2f(float x) {
    float y;
    asm("ex2.approx.ftz.f32 %0, %1;" : "=f"(y) : "f"(x));
    return y;
}

// ---------------------------------------------------------------------------
// C = (A @ W^T + bias) * scale   via bf16x3 split tensor-core GEMM.
// qkv=1: grid.z selects {query->Qtf(tf32,scaled), key->Ktf(tf32), value->V split}
// qkv=0: flat fp32 output Cflat.
// ---------------------------------------------------------------------------
__global__ __launch_bounds__(256) void gemm_mma(const float* __restrict__ A0,
                                                const float* __restrict__ A1,
                                                const float* __restrict__ A2,
                                                const float* __restrict__ W,
                                                const float* __restrict__ bias,
                                                float* __restrict__ Qtf,
                                                float* __restrict__ Ktf,
                                                __nv_bfloat16* __restrict__ Vhb,
                                                __nv_bfloat16* __restrict__ Vlb,
                                                float* __restrict__ Cflat,
                                                float scaleQ, int qkv)
{
    __shared__ __align__(16) __nv_bfloat16 Ah[128 * 40];
    __shared__ __align__(16) __nv_bfloat16 Al[128 * 40];
    __shared__ __align__(16) __nv_bfloat16 Bh[128 * 40];
    __shared__ __align__(16) __nv_bfloat16 Bl[128 * 40];

    const int z = qkv ? blockIdx.z : 0;
    const float* A  = qkv ? (z == 0 ? A0 : (z == 1 ? A1 : A2)) : A0;
    const float* Wz = W + (size_t)z * E_DIM * E_DIM;
    const float* bz = bias + z * E_DIM;
    const int   mode  = qkv ? (z == 2 ? 1 : 2) : 0;
    const float scale = (qkv && z == 0) ? scaleQ : 1.f;
    float* Cf = (z == 0) ? Qtf : Ktf;

    const int tid  = threadIdx.x;
    const int lane = tid & 31;
    const int wid  = tid >> 5;
    const int wm   = wid >> 2;
    const int wn   = wid & 3;
    const int bm   = blockIdx.y << 7;
    const int bn   = blockIdx.x << 7;

    const int lrow  = lane & 15;
    const int lkoff = ((lane >> 4) & 1) << 4;

    const uint32_t sAh = smem_u32(Ah);
    const uint32_t sAl = smem_u32(Al);
    const uint32_t sBh = smem_u32(Bh);
    const uint32_t sBl = smem_u32(Bl);

    float acc[4][4][4];
    #pragma unroll
    for (int i = 0; i < 4; i++)
        #pragma unroll
        for (int j = 0; j < 4; j++)
            #pragma unroll
            for (int r = 0; r < 4; r++) acc[i][j][r] = 0.f;

    int arow[4], ac4[4];
    #pragma unroll
    for (int it = 0; it < 4; it++) {
        int chunk = tid + it * 256;
        arow[it] = chunk >> 3;
        ac4[it]  = (chunk & 7) << 2;
    }

    for (int kt = 0; kt < E_DIM; kt += 32) {
        float4 apre[4], bpre[4];
        #pragma unroll
        for (int it = 0; it < 4; it++) {
            apre[it] = *(const float4*)(A  + (size_t)(bm + arow[it]) * E_DIM + kt + ac4[it]);
            bpre[it] = *(const float4*)(Wz + (size_t)(bn + arow[it]) * E_DIM + kt + ac4[it]);
        }
        __syncthreads();
        #pragma unroll
        for (int it = 0; it < 4; it++) {
            const int off = arow[it] * 40 + ac4[it];
            uint32_t hi, lo;
            split2(apre[it].x, apre[it].y, hi, lo);
            *reinterpret_cast<uint32_t*>(&Ah[off]) = hi;
            *reinterpret_cast<uint32_t*>(&Al[off]) = lo;
            split2(apre[it].z, apre[it].w, hi, lo);
            *reinterpret_cast<uint32_t*>(&Ah[off + 2]) = hi;
            *reinterpret_cast<uint32_t*>(&Al[off + 2]) = lo;
            split2(bpre[it].x, bpre[it].y, hi, lo);
            *reinterpret_cast<uint32_t*>(&Bh[off]) = hi;
            *reinterpret_cast<uint32_t*>(&Bl[off]) = lo;
            split2(bpre[it].z, bpre[it].w, hi, lo);
            *reinterpret_cast<uint32_t*>(&Bh[off + 2]) = hi;
            *reinterpret_cast<uint32_t*>(&Bl[off + 2]) = lo;
        }
        __syncthreads();

        #pragma unroll
        for (int ks = 0; ks < 2; ks++) {
            const int kbyte = ks * 32 + lkoff;
            uint32_t Afh[4][4], Afl[4][4];
            #pragma unroll
            for (int mt = 0; mt < 4; mt++) {
                const uint32_t row = (uint32_t)(wm * 64 + mt * 16 + lrow) * 80 + kbyte;
                ldsm4(Afh[mt], sAh + row);
                ldsm4(Afl[mt], sAl + row);
            }
            uint32_t Bfh[2][4], Bfl[2][4];
            #pragma unroll
            for (int p = 0; p < 2; p++) {
                const uint32_t row = (uint32_t)(wn * 32 + p * 16 + lrow) * 80 + kbyte;
                ldsm4(Bfh[p], sBh + row);
                ldsm4(Bfl[p], sBl + row);
            }
            #pragma unroll
            for (int mt = 0; mt < 4; mt++) {
                #pragma unroll
                for (int nt = 0; nt < 4; nt++) {
                    const int p = nt >> 1, s = nt & 1;
                    const uint32_t b0h = Bfh[p][s ? 1 : 0], b1h = Bfh[p][s ? 3 : 2];
                    const uint32_t b0l = Bfl[p][s ? 1 : 0], b1l = Bfl[p][s ? 3 : 2];
                    mma_bf16(acc[mt][nt], Afh[mt], b0h, b1h);
                    mma_bf16(acc[mt][nt], Afh[mt], b0l, b1l);
                    mma_bf16(acc[mt][nt], Afl[mt], b0h, b1h);
                }
            }
        }
    }

    const int g   = lane >> 2;
    const int tig = lane & 3;
    #pragma unroll
    for (int mt = 0; mt < 4; mt++) {
        #pragma unroll
        for (int nt = 0; nt < 4; nt++) {
            const int m0 = bm + wm * 64 + mt * 16 + g;
            const int n0 = bn + wn * 32 + nt * 8 + tig * 2;
            const float b0 = bz[n0], b1 = bz[n0 + 1];
            float v[4];
            #pragma unroll
            for (int r = 0; r < 4; r++)
                v[r] = (acc[mt][nt][r] + ((r & 1) ? b1 : b0)) * scale;
            if (mode == 1) {
                #pragma unroll
                for (int rr = 0; rr < 2; rr++) {
                    const int m = m0 + rr * 8;
                    const int t = m >> 1;        // B_DIM == 2
                    const int b = m & 1;
                    const int h = n0 >> 6;
                    const int dd = n0 & 63;
                    uint32_t hi, lo;
                    split2(v[rr * 2], v[rr * 2 + 1], hi, lo);
                    const size_t idx = (((size_t)(b * H_DIM + h)) * T_DIM + t) * D_DIM + dd;
                    *reinterpret_cast<uint32_t*>(&Vhb[idx]) = hi;
                    *reinterpret_cast<uint32_t*>(&Vlb[idx]) = lo;
                }
            } else if (mode == 2) {
                #pragma unroll
                for (int rr = 0; rr < 2; rr++) {
                    const int m = m0 + rr * 8;
                    const int t = m >> 1;
                    const int b = m & 1;
                    const int h = n0 >> 6;
                    const int dd = n0 & 63;
                    const size_t idx = (((size_t)(b * H_DIM + h)) * T_DIM + t) * D_DIM + dd;
                    *(float2*)(Cf + idx) = make_float2(to_tf32(v[rr * 2]),
                                                       to_tf32(v[rr * 2 + 1]));
                }
            } else {
                #pragma unroll
                for (int r = 0; r < 4; r++) {
                    const int m = m0 + ((r >> 1) << 3);
                    const int n = n0 + (r & 1);
                    Cflat[(size_t)m * E_DIM + n] = v[r];
                }
            }
        }
    }
}

// ---------------------------------------------------------------------------
// MMA flash attention. Block = 64 queries x 1 head; 4 warps x 16 q-rows.
// QK^T in tf32 (log2e pre-folded into Q), PV in bf16x3. exp2-domain softmax.
// smem: Q(tf32, 64x68f) | K(tf32, 64x68f) | Vh | Vl (bf16, 64x72h)
// ---------------------------------------------------------------------------
#define AOFF_Q  0
#define AOFF_K  17408
#define AOFF_VH 34816
#define AOFF_VL 44032
#define ATT_SMEM 53248

__global__ __launch_bounds__(128, 4) void attn_mma(
    const float* __restrict__ Qtf, const float* __restrict__ Ktf,
    const __nv_bfloat16* __restrict__ Vhb, const __nv_bfloat16* __restrict__ Vlb,
    float* __restrict__ ctx)
{
    extern __shared__ __align__(16) char smraw[];

    const int tid  = threadIdx.x;
    const int lane = tid & 31;
    const int w    = tid >> 5;       // 0..3
    const int qt   = blockIdx.x;     // 0..31
    const int hg   = blockIdx.y;     // 0..31 = b*H + h
    const int lrow = lane & 15;
    const int lk16 = ((lane >> 4) & 1) << 4;
    const int rg   = lane >> 2;
    const int tig  = lane & 3;

    const uint32_t uSM = smem_u32(smraw);

    // ---- stage Q tile (64 rows x 64 tf32, 272B stride) ----
    {
        const uint4* gq = (const uint4*)(Qtf + ((size_t)hg * T_DIM + qt * 64) * D_DIM);
        #pragma unroll
        for (int i = 0; i < 8; i++) {
            int c = tid + i * 128;          // 0..1023
            int row = c >> 4, j = c & 15;
            *(uint4*)(smraw + AOFF_Q + row * 272 + j * 16) = gq[c];
        }
    }

    float o[8][4];
    #pragma unroll
    for (int nt = 0; nt < 8; nt++)
        #pragma unroll
        for (int r = 0; r < 4; r++) o[nt][r] = 0.f;
    float m0 = -CUDART_INF_F, m1 = -CUDART_INF_F, l0 = 0.f, l1 = 0.f;

    const uint4* gK  = (const uint4*)(Ktf + (size_t)hg * T_DIM * D_DIM);
    const uint4* gVh = (const uint4*)(Vhb + (size_t)hg * T_DIM * D_DIM);
    const uint4* gVl = (const uint4*)(Vlb + (size_t)hg * T_DIM * D_DIM);

    for (int st = 0; st < T_DIM / 64; st++) {
        __syncthreads();   // prior tile reads done (st=0: Q staging done)
        // K tile: 64x64 tf32 = 1024 uint4
        #pragma unroll
        for (int i = 0; i < 8; i++) {
            int c = tid + i * 128;
            int row = c >> 4, j = c & 15;
            *(uint4*)(smraw + AOFF_K + row * 272 + j * 16) = gK[st * 1024 + c];
        }
        // V tiles: 64x64 bf16 = 512 uint4 each
        #pragma unroll
        for (int i = 0; i < 4; i++) {
            int c = tid + i * 128;
            int row = c >> 3, j = c & 7;
            int off = row * 144 + j * 16;
            *(uint4*)(smraw + AOFF_VH + off) = gVh[st * 512 + c];
            *(uint4*)(smraw + AOFF_VL + off) = gVl[st * 512 + c];
        }
        __syncthreads();

        // ---- S = Q K^T in tf32; warp tile 16 x 64 ----
        float s[8][4];
        #pragma unroll
        for (int nt = 0; nt < 8; nt++)
            #pragma unroll
            for (int r = 0; r < 4; r++) s[nt][r] = 0.f;

        #pragma unroll
        for (int kk = 0; kk < 8; kk++) {
            uint32_t qa[4];
            ldsm4(qa, uSM + AOFF_Q + (uint32_t)(w * 16 + lrow) * 272 + kk * 32 + lk16);
            uint32_t kf[4][4];
            #pragma unroll
            for (int nb = 0; nb < 4; nb++)
                ldsm4(kf[nb], uSM + AOFF_K + (uint32_t)(nb * 16 + lrow) * 272 + kk * 32 + lk16);
            #pragma unroll
            for (int nb = 0; nb < 4; nb++) {
                mma_tf32(s[2 * nb],     qa, kf[nb][0], kf[nb][2]);
                mma_tf32(s[2 * nb + 1], qa, kf[nb][1], kf[nb][3]);
            }
        }

        // ---- online softmax in exp2 domain ----
        float mx0 = -CUDART_INF_F, mx1 = -CUDART_INF_F;
        #pragma unroll
        for (int nt = 0; nt < 8; nt++) {
            mx0 = fmaxf(mx0, fmaxf(s[nt][0], s[nt][1]));
            mx1 = fmaxf(mx1, fmaxf(s[nt][2], s[nt][3]));
        }
        mx0 = fmaxf(mx0, __shfl_xor_sync(0xffffffffu, mx0, 1));
        mx0 = fmaxf(mx0, __shfl_xor_sync(0xffffffffu, mx0, 2));
        mx1 = fmaxf(mx1, __shfl_xor_sync(0xffffffffu, mx1, 1));
        mx1 = fmaxf(mx1, __shfl_xor_sync(0xffffffffu, mx1, 2));
        const float mn0 = fmaxf(m0, mx0), mn1 = fmaxf(m1, mx1);
        const float al0 = ex2f(m0 - mn0), al1 = ex2f(m1 - mn1);
        m0 = mn0; m1 = mn1;
        float sum0 = 0.f, sum1 = 0.f;
        #pragma unroll
        for (int nt = 0; nt < 8; nt++) {
            s[nt][0] = ex2f(s[nt][0] - m0);
            s[nt][1] = ex2f(s[nt][1] - m0);
            s[nt][2] = ex2f(s[nt][2] - m1);
            s[nt][3] = ex2f(s[nt][3] - m1);
            sum0 += s[nt][0] + s[nt][1];
            sum1 += s[nt][2] + s[nt][3];
        }
        sum0 += __shfl_xor_sync(0xffffffffu, sum0, 1);
        sum0 += __shfl_xor_sync(0xffffffffu, sum0, 2);
        sum1 += __shfl_xor_sync(0xffffffffu, sum1, 1);
        sum1 += __shfl_xor_sync(0xffffffffu, sum1, 2);
        l0 = l0 * al0 + sum0;
        l1 = l1 * al1 + sum1;
        #pragma unroll
        for (int nt = 0; nt < 8; nt++) {
            o[nt][0] *= al0; o[nt][1] *= al0;
            o[nt][2] *= al1; o[nt][3] *= al1;
        }

        // ---- P accum -> bf16 hi/lo A fragments ----
        uint32_t AH[4][4], AL[4][4];
        #pragma unroll
        for (int kb = 0; kb < 4; kb++) {
            const int t0 = 2 * kb, t1 = 2 * kb + 1;
            split2(s[t0][0], s[t0][1], AH[kb][0], AL[kb][0]);
            split2(s[t0][2], s[t0][3], AH[kb][1], AL[kb][1]);
            split2(s[t1][0], s[t1][1], AH[kb][2], AL[kb][2]);
            split2(s[t1][2], s[t1][3], AH[kb][3], AL[kb][3]);
        }

        // ---- O += P V (bf16x3) ----
        #pragma unroll
        for (int kb = 0; kb < 4; kb++) {
            uint32_t vh[4][4], vl[4][4];
            #pragma unroll
            for (int db = 0; db < 4; db++) {
                const uint32_t a = uSM + AOFF_VH + (uint32_t)(kb * 16 + lrow) * 144 + db * 32 + lk16;
                ldsm4t(vh[db], a);
                ldsm4t(vl[db], a + (AOFF_VL - AOFF_VH));
            }
            #pragma unroll
            for (int db = 0; db < 4; db++) {
                #pragma unroll
                for (int hs = 0; hs < 2; hs++) {
                    const int nt = db * 2 + hs;
                    const uint32_t b0h = vh[db][hs * 2], b1h = vh[db][hs * 2 + 1];
                    mma_bf16(o[nt], AH[kb], b0h, b1h);
                    mma_bf16(o[nt], AL[kb], b0h, b1h);
                    mma_bf16(o[nt], AH[kb], vl[db][hs * 2], vl[db][hs * 2 + 1]);
                }
            }
        }
    }

    // ---- epilogue ----
    const float inv0 = 1.f / l0, inv1 = 1.f / l1;
    const int bb = hg >> 4;
    const int hh = hg & 15;
    const int q0 = qt * 64 + w * 16 + rg;
    #pragma unroll
    for (int nt = 0; nt < 8; nt++) {
        const int d = hh * 64 + nt * 8 + tig * 2;
        *(float2*)(ctx + ((size_t)q0 * B_DIM + bb) * E_DIM + d) =
            make_float2(o[nt][0] * inv0, o[nt][1] * inv0);
        *(float2*)(ctx + ((size_t)(q0 + 8) * B_DIM + bb) * E_DIM + d) =
            make_float2(o[nt][2] * inv1, o[nt][3] * inv1);
    }
}

// ---------------------------------------------------------------------------
extern "C" void kernel_launch(void* const* d_in, const int* in_sizes, int n_in,
                              void* d_out, int out_size)
{
    const float* query = (const float*)d_in[0];
    const float* key   = (const float*)d_in[1];
    const float* value = (const float*)d_in[2];
    const float* Win   = (const float*)d_in[3];   // (3E, E)
    const float* bin   = (const float*)d_in[4];   // (3E,)
    const float* Wout  = (const float*)d_in[5];   // (E, E)
    const float* bout  = (const float*)d_in[6];   // (E,)
    float* out = (float*)d_out;

    float *Qtf, *Ktf, *ctx;
    __nv_bfloat16 *Vhb, *Vlb;
    cudaGetSymbolAddress((void**)&Qtf, g_Qtf);
    cudaGetSymbolAddress((void**)&Ktf, g_Ktf);
    cudaGetSymbolAddress((void**)&Vhb, g_Vhb);
    cudaGetSymbolAddress((void**)&Vlb, g_Vlb);
    cudaGetSymbolAddress((void**)&ctx, g_ctx);

    const float scaleQ = 0.125f * 1.44269504089f;   // 1/sqrt(64) * log2(e)

    // QKV projections, batched over grid.z
    gemm_mma<<<dim3(E_DIM / 128, NROWS / 128, 3), 256>>>(
        query, key, value, Win, bin, Qtf, Ktf, Vhb, Vlb, nullptr, scaleQ, 1);

    cudaFuncSetAttribute(attn_mma, cudaFuncAttributeMaxDynamicSharedMemorySize, ATT_SMEM);
    attn_mma<<<dim3(T_DIM / 64, NHEADS), 128, ATT_SMEM>>>(Qtf, Ktf, Vhb, Vlb, ctx);

    // out projection (flat fp32)
    gemm_mma<<<dim3(E_DIM / 128, NROWS / 128, 1), 256>>>(
        ctx, nullptr, nullptr, Wout, bout, nullptr, nullptr, nullptr, nullptr, out, 1.f, 0);
}

// round 6
// speedup vs baseline: 6.2366x; 1.1760x over previous
#include <cuda_runtime.h>
#include <cuda_bf16.h>
#include <math_constants.h>
#include <cstdint>

#define T_DIM 2048
#define B_DIM 2
#define E_DIM 1024
#define H_DIM 16
#define D_DIM 64
#define NHEADS (B_DIM * H_DIM)          // 32
#define NROWS  (T_DIM * B_DIM)          // 4096

// Scratch (device globals; no runtime allocation)
__device__ float         g_Qtf[NHEADS * T_DIM * D_DIM];   // tf32-rounded, scale*log2e folded
__device__ float         g_Ktf[NHEADS * T_DIM * D_DIM];   // tf32-rounded
__device__ __nv_bfloat16 g_Vhb[NHEADS * T_DIM * D_DIM];
__device__ __nv_bfloat16 g_Vlb[NHEADS * T_DIM * D_DIM];
__device__ float         g_ctx[NROWS * E_DIM];            // (T, B, E)

// ---------------------------------------------------------------------------
// helpers
// ---------------------------------------------------------------------------
__device__ __forceinline__ void ldsm4(uint32_t* r, uint32_t addr) {
    asm volatile("ldmatrix.sync.aligned.m8n8.x4.shared.b16 {%0,%1,%2,%3}, [%4];"
                 : "=r"(r[0]), "=r"(r[1]), "=r"(r[2]), "=r"(r[3]) : "r"(addr));
}
__device__ __forceinline__ void ldsm4t(uint32_t* r, uint32_t addr) {
    asm volatile("ldmatrix.sync.aligned.m8n8.x4.trans.shared.b16 {%0,%1,%2,%3}, [%4];"
                 : "=r"(r[0]), "=r"(r[1]), "=r"(r[2]), "=r"(r[3]) : "r"(addr));
}
__device__ __forceinline__ void mma_bf16(float* d, const uint32_t* a,
                                         uint32_t b0, uint32_t b1) {
    asm volatile("mma.sync.aligned.m16n8k16.row.col.f32.bf16.bf16.f32 "
                 "{%0,%1,%2,%3}, {%4,%5,%6,%7}, {%8,%9}, {%0,%1,%2,%3};"
                 : "+f"(d[0]), "+f"(d[1]), "+f"(d[2]), "+f"(d[3])
                 : "r"(a[0]), "r"(a[1]), "r"(a[2]), "r"(a[3]), "r"(b0), "r"(b1));
}
__device__ __forceinline__ void mma_tf32(float* d, const uint32_t* a,
                                         uint32_t b0, uint32_t b1) {
    asm volatile("mma.sync.aligned.m16n8k8.row.col.f32.tf32.tf32.f32 "
                 "{%0,%1,%2,%3}, {%4,%5,%6,%7}, {%8,%9}, {%0,%1,%2,%3};"
                 : "+f"(d[0]), "+f"(d[1]), "+f"(d[2]), "+f"(d[3])
                 : "r"(a[0]), "r"(a[1]), "r"(a[2]), "r"(a[3]), "r"(b0), "r"(b1));
}
__device__ __forceinline__ uint32_t smem_u32(const void* p) {
    return (uint32_t)__cvta_generic_to_shared(p);
}
__device__ __forceinline__ uint32_t pack_bf16(__nv_bfloat16 x, __nv_bfloat16 y) {
    __nv_bfloat162 v = __halves2bfloat162(x, y);
    return *reinterpret_cast<uint32_t*>(&v);
}
__device__ __forceinline__ void split2(float a, float b, uint32_t& hi, uint32_t& lo) {
    __nv_bfloat16 ha = __float2bfloat16(a), hb = __float2bfloat16(b);
    hi = pack_bf16(ha, hb);
    lo = pack_bf16(__float2bfloat16(a - __bfloat162float(ha)),
                   __float2bfloat16(b - __bfloat162float(hb)));
}
__device__ __forceinline__ float to_tf32(float x) {
    uint32_t r;
    asm("cvt.rna.tf32.f32 %0, %1;" : "=r"(r) : "f"(x));
    return __uint_as_float(r);
}
__device__ __forceinline__ float ex2f(float x) {
    float y;
    asm("ex2.approx.ftz.f32 %0, %1;" : "=f"(y) : "f"(x));
    return y;
}

// ---------------------------------------------------------------------------
// Single-pass tf32 GEMM: C = (A @ W^T + bias) * scale
// A: [4096,1024] row-major fp32, W: [1024,1024] row-major fp32.
// Block tile 128x128, K-tile 32, 256 threads (8 warps 2Mx4N), double-buffered.
// smem rows: 32 tf32 + pad, stride 144B. Dynamic smem 72KB.
// qkv=1: grid.z -> {Q->Qtf(tf32,scaled), K->Ktf(tf32), V->bf16 hi/lo split}
// qkv=0: flat fp32 Cflat.
// ---------------------------------------------------------------------------
#define GT 18432                 // one tile: 128 rows * 144B
#define GSMEM (4 * GT)           // A0,W0,A1,W1 = 73728

__global__ __launch_bounds__(256, 2) void gemm_tf32(const float* __restrict__ A0,
                                                    const float* __restrict__ A1,
                                                    const float* __restrict__ A2,
                                                    const float* __restrict__ W,
                                                    const float* __restrict__ bias,
                                                    float* __restrict__ Qtf,
                                                    float* __restrict__ Ktf,
                                                    __nv_bfloat16* __restrict__ Vhb,
                                                    __nv_bfloat16* __restrict__ Vlb,
                                                    float* __restrict__ Cflat,
                                                    float scaleQ, int qkv)
{
    extern __shared__ __align__(16) char gsm[];

    const int z = qkv ? blockIdx.z : 0;
    const float* A  = qkv ? (z == 0 ? A0 : (z == 1 ? A1 : A2)) : A0;
    const float* Wz = W + (size_t)z * E_DIM * E_DIM;
    const float* bz = bias + z * E_DIM;
    const int   mode  = qkv ? (z == 2 ? 1 : 2) : 0;
    const float scale = (qkv && z == 0) ? scaleQ : 1.f;
    float* Cf = (z == 0) ? Qtf : Ktf;

    const int tid  = threadIdx.x;
    const int lane = tid & 31;
    const int wid  = tid >> 5;
    const int wm   = wid >> 2;      // 0..1
    const int wn   = wid & 3;       // 0..3
    const int bm   = blockIdx.y << 7;
    const int bn   = blockIdx.x << 7;

    const int lrow = lane & 15;
    const int lk16 = ((lane >> 4) & 1) << 4;
    const uint32_t uS = smem_u32(gsm);

    float acc[4][4][4];
    #pragma unroll
    for (int i = 0; i < 4; i++)
        #pragma unroll
        for (int j = 0; j < 4; j++)
            #pragma unroll
            for (int r = 0; r < 4; r++) acc[i][j][r] = 0.f;

    // chunk mapping: 1024 float4 chunks per tensor tile, 4 per thread
    int crow[4], cj[4];
    #pragma unroll
    for (int it = 0; it < 4; it++) {
        int c = tid + it * 256;
        crow[it] = c >> 3;          // 0..127
        cj[it]   = (c & 7) << 2;    // float offset 0,4,..,28
    }

    // ---- preload k-tile 0 into buffer 0 ----
    #pragma unroll
    for (int it = 0; it < 4; it++) {
        float4 av = *(const float4*)(A  + (size_t)(bm + crow[it]) * E_DIM + cj[it]);
        float4 wv = *(const float4*)(Wz + (size_t)(bn + crow[it]) * E_DIM + cj[it]);
        const int off = crow[it] * 144 + cj[it] * 4;
        *(float4*)(gsm + off)      = make_float4(to_tf32(av.x), to_tf32(av.y), to_tf32(av.z), to_tf32(av.w));
        *(float4*)(gsm + GT + off) = make_float4(to_tf32(wv.x), to_tf32(wv.y), to_tf32(wv.z), to_tf32(wv.w));
    }
    __syncthreads();

    const int NK = E_DIM / 32;     // 32
    for (int kt = 0; kt < NK; kt++) {
        const int p = kt & 1;
        const uint32_t pA = uS + (uint32_t)(2 * p) * GT;
        const uint32_t pW = pA + GT;

        // prefetch next tile
        float4 apre[4], bpre[4];
        if (kt + 1 < NK) {
            const int kc = (kt + 1) * 32;
            #pragma unroll
            for (int it = 0; it < 4; it++) {
                apre[it] = *(const float4*)(A  + (size_t)(bm + crow[it]) * E_DIM + kc + cj[it]);
                bpre[it] = *(const float4*)(Wz + (size_t)(bn + crow[it]) * E_DIM + kc + cj[it]);
            }
        }

        // compute on buffer p
        #pragma unroll
        for (int kk = 0; kk < 4; kk++) {
            uint32_t Af[4][4];
            #pragma unroll
            for (int mt = 0; mt < 4; mt++)
                ldsm4(Af[mt], pA + (uint32_t)(wm * 64 + mt * 16 + lrow) * 144 + kk * 32 + lk16);
            uint32_t Bf[2][4];
            #pragma unroll
            for (int nb = 0; nb < 2; nb++)
                ldsm4(Bf[nb], pW + (uint32_t)(wn * 32 + nb * 16 + lrow) * 144 + kk * 32 + lk16);
            #pragma unroll
            for (int mt = 0; mt < 4; mt++) {
                #pragma unroll
                for (int nt = 0; nt < 4; nt++) {
                    const int nb = nt >> 1, hf = nt & 1;
                    mma_tf32(acc[mt][nt], Af[mt], Bf[nb][hf], Bf[nb][hf + 2]);
                }
            }
        }

        // store prefetched tile into the other buffer
        if (kt + 1 < NK) {
            const uint32_t qA = (uint32_t)(2 * (1 - p)) * GT;
            #pragma unroll
            for (int it = 0; it < 4; it++) {
                const int off = crow[it] * 144 + cj[it] * 4;
                *(float4*)(gsm + qA + off)      = make_float4(to_tf32(apre[it].x), to_tf32(apre[it].y),
                                                              to_tf32(apre[it].z), to_tf32(apre[it].w));
                *(float4*)(gsm + qA + GT + off) = make_float4(to_tf32(bpre[it].x), to_tf32(bpre[it].y),
                                                              to_tf32(bpre[it].z), to_tf32(bpre[it].w));
            }
        }
        __syncthreads();
    }

    // ---- epilogue ----
    const int g   = lane >> 2;
    const int tig = lane & 3;
    #pragma unroll
    for (int mt = 0; mt < 4; mt++) {
        #pragma unroll
        for (int nt = 0; nt < 4; nt++) {
            const int m0 = bm + wm * 64 + mt * 16 + g;
            const int n0 = bn + wn * 32 + nt * 8 + tig * 2;
            const float b0 = bz[n0], b1 = bz[n0 + 1];
            float v[4];
            #pragma unroll
            for (int r = 0; r < 4; r++)
                v[r] = (acc[mt][nt][r] + ((r & 1) ? b1 : b0)) * scale;
            if (mode == 1) {
                #pragma unroll
                for (int rr = 0; rr < 2; rr++) {
                    const int m = m0 + rr * 8;
                    const int t = m >> 1;        // B_DIM == 2
                    const int b = m & 1;
                    const int h = n0 >> 6;
                    const int dd = n0 & 63;
                    uint32_t hi, lo;
                    split2(v[rr * 2], v[rr * 2 + 1], hi, lo);
                    const size_t idx = (((size_t)(b * H_DIM + h)) * T_DIM + t) * D_DIM + dd;
                    *reinterpret_cast<uint32_t*>(&Vhb[idx]) = hi;
                    *reinterpret_cast<uint32_t*>(&Vlb[idx]) = lo;
                }
            } else if (mode == 2) {
                #pragma unroll
                for (int rr = 0; rr < 2; rr++) {
                    const int m = m0 + rr * 8;
                    const int t = m >> 1;
                    const int b = m & 1;
                    const int h = n0 >> 6;
                    const int dd = n0 & 63;
                    const size_t idx = (((size_t)(b * H_DIM + h)) * T_DIM + t) * D_DIM + dd;
                    *(float2*)(Cf + idx) = make_float2(to_tf32(v[0 + rr * 2]),
                                                       to_tf32(v[1 + rr * 2]));
                }
            } else {
                #pragma unroll
                for (int r = 0; r < 4; r++) {
                    const int m = m0 + ((r >> 1) << 3);
                    const int n = n0 + (r & 1);
                    Cflat[(size_t)m * E_DIM + n] = v[r];
                }
            }
        }
    }
}

// ---------------------------------------------------------------------------
// MMA flash attention (unchanged from round 5). Block = 64 queries x 1 head.
// QK^T in tf32 (log2e folded into Q), PV in bf16x3, exp2 softmax.
// ---------------------------------------------------------------------------
#define AOFF_Q  0
#define AOFF_K  17408
#define AOFF_VH 34816
#define AOFF_VL 44032
#define ATT_SMEM 53248

__global__ __launch_bounds__(128, 4) void attn_mma(
    const float* __restrict__ Qtf, const float* __restrict__ Ktf,
    const __nv_bfloat16* __restrict__ Vhb, const __nv_bfloat16* __restrict__ Vlb,
    float* __restrict__ ctx)
{
    extern __shared__ __align__(16) char smraw[];

    const int tid  = threadIdx.x;
    const int lane = tid & 31;
    const int w    = tid >> 5;       // 0..3
    const int qt   = blockIdx.x;     // 0..31
    const int hg   = blockIdx.y;     // 0..31 = b*H + h
    const int lrow = lane & 15;
    const int lk16 = ((lane >> 4) & 1) << 4;
    const int rg   = lane >> 2;
    const int tig  = lane & 3;

    const uint32_t uSM = smem_u32(smraw);

    {
        const uint4* gq = (const uint4*)(Qtf + ((size_t)hg * T_DIM + qt * 64) * D_DIM);
        #pragma unroll
        for (int i = 0; i < 8; i++) {
            int c = tid + i * 128;
            int row = c >> 4, j = c & 15;
            *(uint4*)(smraw + AOFF_Q + row * 272 + j * 16) = gq[c];
        }
    }

    float o[8][4];
    #pragma unroll
    for (int nt = 0; nt < 8; nt++)
        #pragma unroll
        for (int r = 0; r < 4; r++) o[nt][r] = 0.f;
    float m0 = -CUDART_INF_F, m1 = -CUDART_INF_F, l0 = 0.f, l1 = 0.f;

    const uint4* gK  = (const uint4*)(Ktf + (size_t)hg * T_DIM * D_DIM);
    const uint4* gVh = (const uint4*)(Vhb + (size_t)hg * T_DIM * D_DIM);
    const uint4* gVl = (const uint4*)(Vlb + (size_t)hg * T_DIM * D_DIM);

    for (int st = 0; st < T_DIM / 64; st++) {
        __syncthreads();
        #pragma unroll
        for (int i = 0; i < 8; i++) {
            int c = tid + i * 128;
            int row = c >> 4, j = c & 15;
            *(uint4*)(smraw + AOFF_K + row * 272 + j * 16) = gK[st * 1024 + c];
        }
        #pragma unroll
        for (int i = 0; i < 4; i++) {
            int c = tid + i * 128;
            int row = c >> 3, j = c & 7;
            int off = row * 144 + j * 16;
            *(uint4*)(smraw + AOFF_VH + off) = gVh[st * 512 + c];
            *(uint4*)(smraw + AOFF_VL + off) = gVl[st * 512 + c];
        }
        __syncthreads();

        float s[8][4];
        #pragma unroll
        for (int nt = 0; nt < 8; nt++)
            #pragma unroll
            for (int r = 0; r < 4; r++) s[nt][r] = 0.f;

        #pragma unroll
        for (int kk = 0; kk < 8; kk++) {
            uint32_t qa[4];
            ldsm4(qa, uSM + AOFF_Q + (uint32_t)(w * 16 + lrow) * 272 + kk * 32 + lk16);
            uint32_t kf[4][4];
            #pragma unroll
            for (int nb = 0; nb < 4; nb++)
                ldsm4(kf[nb], uSM + AOFF_K + (uint32_t)(nb * 16 + lrow) * 272 + kk * 32 + lk16);
            #pragma unroll
            for (int nb = 0; nb < 4; nb++) {
                mma_tf32(s[2 * nb],     qa, kf[nb][0], kf[nb][2]);
                mma_tf32(s[2 * nb + 1], qa, kf[nb][1], kf[nb][3]);
            }
        }

        float mx0 = -CUDART_INF_F, mx1 = -CUDART_INF_F;
        #pragma unroll
        for (int nt = 0; nt < 8; nt++) {
            mx0 = fmaxf(mx0, fmaxf(s[nt][0], s[nt][1]));
            mx1 = fmaxf(mx1, fmaxf(s[nt][2], s[nt][3]));
        }
        mx0 = fmaxf(mx0, __shfl_xor_sync(0xffffffffu, mx0, 1));
        mx0 = fmaxf(mx0, __shfl_xor_sync(0xffffffffu, mx0, 2));
        mx1 = fmaxf(mx1, __shfl_xor_sync(0xffffffffu, mx1, 1));
        mx1 = fmaxf(mx1, __shfl_xor_sync(0xffffffffu, mx1, 2));
        const float mn0 = fmaxf(m0, mx0), mn1 = fmaxf(m1, mx1);
        const float al0 = ex2f(m0 - mn0), al1 = ex2f(m1 - mn1);
        m0 = mn0; m1 = mn1;
        float sum0 = 0.f, sum1 = 0.f;
        #pragma unroll
        for (int nt = 0; nt < 8; nt++) {
            s[nt][0] = ex2f(s[nt][0] - m0);
            s[nt][1] = ex2f(s[nt][1] - m0);
            s[nt][2] = ex2f(s[nt][2] - m1);
            s[nt][3] = ex2f(s[nt][3] - m1);
            sum0 += s[nt][0] + s[nt][1];
            sum1 += s[nt][2] + s[nt][3];
        }
        sum0 += __shfl_xor_sync(0xffffffffu, sum0, 1);
        sum0 += __shfl_xor_sync(0xffffffffu, sum0, 2);
        sum1 += __shfl_xor_sync(0xffffffffu, sum1, 1);
        sum1 += __shfl_xor_sync(0xffffffffu, sum1, 2);
        l0 = l0 * al0 + sum0;
        l1 = l1 * al1 + sum1;
        #pragma unroll
        for (int nt = 0; nt < 8; nt++) {
            o[nt][0] *= al0; o[nt][1] *= al0;
            o[nt][2] *= al1; o[nt][3] *= al1;
        }

        uint32_t AH[4][4], AL[4][4];
        #pragma unroll
        for (int kb = 0; kb < 4; kb++) {
            const int t0 = 2 * kb, t1 = 2 * kb + 1;
            split2(s[t0][0], s[t0][1], AH[kb][0], AL[kb][0]);
            split2(s[t0][2], s[t0][3], AH[kb][1], AL[kb][1]);
            split2(s[t1][0], s[t1][1], AH[kb][2], AL[kb][2]);
            split2(s[t1][2], s[t1][3], AH[kb][3], AL[kb][3]);
        }

        #pragma unroll
        for (int kb = 0; kb < 4; kb++) {
            uint32_t vh[4][4], vl[4][4];
            #pragma unroll
            for (int db = 0; db < 4; db++) {
                const uint32_t a = uSM + AOFF_VH + (uint32_t)(kb * 16 + lrow) * 144 + db * 32 + lk16;
                ldsm4t(vh[db], a);
                ldsm4t(vl[db], a + (AOFF_VL - AOFF_VH));
            }
            #pragma unroll
            for (int db = 0; db < 4; db++) {
                #pragma unroll
                for (int hs = 0; hs < 2; hs++) {
                    const int nt = db * 2 + hs;
                    const uint32_t b0h = vh[db][hs * 2], b1h = vh[db][hs * 2 + 1];
                    mma_bf16(o[nt], AH[kb], b0h, b1h);
                    mma_bf16(o[nt], AL[kb], b0h, b1h);
                    mma_bf16(o[nt], AH[kb], vl[db][hs * 2], vl[db][hs * 2 + 1]);
                }
            }
        }
    }

    const float inv0 = 1.f / l0, inv1 = 1.f / l1;
    const int bb = hg >> 4;
    const int hh = hg & 15;
    const int q0 = qt * 64 + w * 16 + rg;
    #pragma unroll
    for (int nt = 0; nt < 8; nt++) {
        const int d = hh * 64 + nt * 8 + tig * 2;
        *(float2*)(ctx + ((size_t)q0 * B_DIM + bb) * E_DIM + d) =
            make_float2(o[nt][0] * inv0, o[nt][1] * inv0);
        *(float2*)(ctx + ((size_t)(q0 + 8) * B_DIM + bb) * E_DIM + d) =
            make_float2(o[nt][2] * inv1, o[nt][3] * inv1);
    }
}

// ---------------------------------------------------------------------------
extern "C" void kernel_launch(void* const* d_in, const int* in_sizes, int n_in,
                              void* d_out, int out_size)
{
    const float* query = (const float*)d_in[0];
    const float* key   = (const float*)d_in[1];
    const float* value = (const float*)d_in[2];
    const float* Win   = (const float*)d_in[3];   // (3E, E)
    const float* bin   = (const float*)d_in[4];   // (3E,)
    const float* Wout  = (const float*)d_in[5];   // (E, E)
    const float* bout  = (const float*)d_in[6];   // (E,)
    float* out = (float*)d_out;

    float *Qtf, *Ktf, *ctx;
    __nv_bfloat16 *Vhb, *Vlb;
    cudaGetSymbolAddress((void**)&Qtf, g_Qtf);
    cudaGetSymbolAddress((void**)&Ktf, g_Ktf);
    cudaGetSymbolAddress((void**)&Vhb, g_Vhb);
    cudaGetSymbolAddress((void**)&Vlb, g_Vlb);
    cudaGetSymbolAddress((void**)&ctx, g_ctx);

    const float scaleQ = 0.125f * 1.44269504089f;   // 1/sqrt(64) * log2(e)

    cudaFuncSetAttribute(gemm_tf32, cudaFuncAttributeMaxDynamicSharedMemorySize, GSMEM);
    cudaFuncSetAttribute(attn_mma,  cudaFuncAttributeMaxDynamicSharedMemorySize, ATT_SMEM);

    // QKV projections, batched over grid.z
    gemm_tf32<<<dim3(E_DIM / 128, NROWS / 128, 3), 256, GSMEM>>>(
        query, key, value, Win, bin, Qtf, Ktf, Vhb, Vlb, nullptr, scaleQ, 1);

    attn_mma<<<dim3(T_DIM / 64, NHEADS), 128, ATT_SMEM>>>(Qtf, Ktf, Vhb, Vlb, ctx);

    // out projection (flat fp32)
    gemm_tf32<<<dim3(E_DIM / 128, NROWS / 128, 1), 256, GSMEM>>>(
        ctx, nullptr, nullptr, Wout, bout, nullptr, nullptr, nullptr, nullptr, out, 1.f, 0);
}

// round 7
// speedup vs baseline: 6.5747x; 1.0542x over previous
#include <cuda_runtime.h>
#include <cuda_bf16.h>
#include <math_constants.h>
#include <cstdint>

#define T_DIM 2048
#define B_DIM 2
#define E_DIM 1024
#define H_DIM 16
#define D_DIM 64
#define NHEADS (B_DIM * H_DIM)          // 32
#define NROWS  (T_DIM * B_DIM)          // 4096

// Scratch (device globals; no runtime allocation)
__device__ float         g_Qtf[NHEADS * T_DIM * D_DIM];   // tf32-rounded, scale*log2e folded
__device__ float         g_Ktf[NHEADS * T_DIM * D_DIM];   // tf32-rounded
__device__ __nv_bfloat16 g_Vhb[NHEADS * T_DIM * D_DIM];
__device__ __nv_bfloat16 g_Vlb[NHEADS * T_DIM * D_DIM];
__device__ float         g_ctx[NROWS * E_DIM];            // (T, B, E)

// ---------------------------------------------------------------------------
// helpers
// ---------------------------------------------------------------------------
__device__ __forceinline__ void ldsm4(uint32_t* r, uint32_t addr) {
    asm volatile("ldmatrix.sync.aligned.m8n8.x4.shared.b16 {%0,%1,%2,%3}, [%4];"
                 : "=r"(r[0]), "=r"(r[1]), "=r"(r[2]), "=r"(r[3]) : "r"(addr));
}
__device__ __forceinline__ void ldsm4t(uint32_t* r, uint32_t addr) {
    asm volatile("ldmatrix.sync.aligned.m8n8.x4.trans.shared.b16 {%0,%1,%2,%3}, [%4];"
                 : "=r"(r[0]), "=r"(r[1]), "=r"(r[2]), "=r"(r[3]) : "r"(addr));
}
__device__ __forceinline__ void mma_bf16(float* d, const uint32_t* a,
                                         uint32_t b0, uint32_t b1) {
    asm volatile("mma.sync.aligned.m16n8k16.row.col.f32.bf16.bf16.f32 "
                 "{%0,%1,%2,%3}, {%4,%5,%6,%7}, {%8,%9}, {%0,%1,%2,%3};"
                 : "+f"(d[0]), "+f"(d[1]), "+f"(d[2]), "+f"(d[3])
                 : "r"(a[0]), "r"(a[1]), "r"(a[2]), "r"(a[3]), "r"(b0), "r"(b1));
}
__device__ __forceinline__ void mma_tf32(float* d, const uint32_t* a,
                                         uint32_t b0, uint32_t b1) {
    asm volatile("mma.sync.aligned.m16n8k8.row.col.f32.tf32.tf32.f32 "
                 "{%0,%1,%2,%3}, {%4,%5,%6,%7}, {%8,%9}, {%0,%1,%2,%3};"
                 : "+f"(d[0]), "+f"(d[1]), "+f"(d[2]), "+f"(d[3])
                 : "r"(a[0]), "r"(a[1]), "r"(a[2]), "r"(a[3]), "r"(b0), "r"(b1));
}
__device__ __forceinline__ uint32_t smem_u32(const void* p) {
    return (uint32_t)__cvta_generic_to_shared(p);
}
__device__ __forceinline__ void cp_async16(uint32_t dst, const void* src) {
    asm volatile("cp.async.cg.shared.global [%0], [%1], 16;"
                 :: "r"(dst), "l"(src));
}
__device__ __forceinline__ void cp_commit() {
    asm volatile("cp.async.commit_group;");
}
template <int N>
__device__ __forceinline__ void cp_wait() {
    asm volatile("cp.async.wait_group %0;" :: "n"(N));
}
__device__ __forceinline__ uint32_t pack_bf16(__nv_bfloat16 x, __nv_bfloat16 y) {
    __nv_bfloat162 v = __halves2bfloat162(x, y);
    return *reinterpret_cast<uint32_t*>(&v);
}
__device__ __forceinline__ void split2(float a, float b, uint32_t& hi, uint32_t& lo) {
    __nv_bfloat16 ha = __float2bfloat16(a), hb = __float2bfloat16(b);
    hi = pack_bf16(ha, hb);
    lo = pack_bf16(__float2bfloat16(a - __bfloat162float(ha)),
                   __float2bfloat16(b - __bfloat162float(hb)));
}
__device__ __forceinline__ float to_tf32(float x) {
    uint32_t r;
    asm("cvt.rna.tf32.f32 %0, %1;" : "=r"(r) : "f"(x));
    return __uint_as_float(r);
}
__device__ __forceinline__ float ex2f(float x) {
    float y;
    asm("ex2.approx.ftz.f32 %0, %1;" : "=f"(y) : "f"(x));
    return y;
}

// ---------------------------------------------------------------------------
// tf32 GEMM with 3-stage cp.async pipeline: C = (A @ W^T + bias) * scale
// A: [4096,1024] fp32 row-major, W: [1024,1024] fp32 row-major.
// Inputs land raw in smem; tf32 MMA truncates low mantissa bits implicitly.
// Block tile 128x128, K-tile 32, 256 threads (8 warps 2Mx4N).
// smem per stage: A(128x144B) + W(128x144B) = 36KB, 3 stages = 108KB dynamic.
// qkv=1: grid.z -> {Q->Qtf(tf32,scaled), K->Ktf(tf32), V->bf16 hi/lo split}
// qkv=0: flat fp32 Cflat.
// ---------------------------------------------------------------------------
#define GT 18432                 // one tensor tile: 128 rows * 144B
#define GSTAGE (2 * GT)          // A + W
#define GSMEM (3 * GSTAGE)       // 110592

__global__ __launch_bounds__(256, 2) void gemm_tf32(const float* __restrict__ A0,
                                                    const float* __restrict__ A1,
                                                    const float* __restrict__ A2,
                                                    const float* __restrict__ W,
                                                    const float* __restrict__ bias,
                                                    float* __restrict__ Qtf,
                                                    float* __restrict__ Ktf,
                                                    __nv_bfloat16* __restrict__ Vhb,
                                                    __nv_bfloat16* __restrict__ Vlb,
                                                    float* __restrict__ Cflat,
                                                    float scaleQ, int qkv)
{
    extern __shared__ __align__(16) char gsm[];

    const int z = qkv ? blockIdx.z : 0;
    const float* A  = qkv ? (z == 0 ? A0 : (z == 1 ? A1 : A2)) : A0;
    const float* Wz = W + (size_t)z * E_DIM * E_DIM;
    const float* bz = bias + z * E_DIM;
    const int   mode  = qkv ? (z == 2 ? 1 : 2) : 0;
    const float scale = (qkv && z == 0) ? scaleQ : 1.f;
    float* Cf = (z == 0) ? Qtf : Ktf;

    const int tid  = threadIdx.x;
    const int lane = tid & 31;
    const int wid  = tid >> 5;
    const int wm   = wid >> 2;      // 0..1
    const int wn   = wid & 3;       // 0..3
    const int bm   = blockIdx.y << 7;
    const int bn   = blockIdx.x << 7;

    const int lrow = lane & 15;
    const int lk16 = ((lane >> 4) & 1) << 4;
    const uint32_t uS = smem_u32(gsm);

    float acc[4][4][4];
    #pragma unroll
    for (int i = 0; i < 4; i++)
        #pragma unroll
        for (int j = 0; j < 4; j++)
            #pragma unroll
            for (int r = 0; r < 4; r++) acc[i][j][r] = 0.f;

    // copy mapping: 1024 16B-chunks per tensor tile, 4 per thread
    const int crow0 = tid >> 3;          // rows tid/8, +32 per it
    const int cjf   = (tid & 7) << 2;    // float offset 0..28
    const float* gA = A  + (size_t)bm * E_DIM;
    const float* gW = Wz + (size_t)bn * E_DIM;

    // ---- prologue: issue stages 0 and 1 ----
    #pragma unroll
    for (int s = 0; s < 2; s++) {
        const uint32_t dst = uS + (uint32_t)s * GSTAGE;
        const int kc = s * 32;
        #pragma unroll
        for (int it = 0; it < 4; it++) {
            const int row = crow0 + it * 32;
            const uint32_t off = (uint32_t)row * 144 + (uint32_t)cjf * 4;
            cp_async16(dst + off,      gA + (size_t)row * E_DIM + kc + cjf);
            cp_async16(dst + GT + off, gW + (size_t)row * E_DIM + kc + cjf);
        }
        cp_commit();
    }

    const int NK = E_DIM / 32;     // 32
    for (int kt = 0; kt < NK; kt++) {
        cp_wait<1>();              // stage kt resident
        __syncthreads();           // all warps see it; all done computing kt-1

        // issue stage kt+2 (reuses buffer of kt-1; barrier above ordered that)
        if (kt + 2 < NK) {
            const uint32_t dst = uS + (uint32_t)((kt + 2) % 3) * GSTAGE;
            const int kc = (kt + 2) * 32;
            #pragma unroll
            for (int it = 0; it < 4; it++) {
                const int row = crow0 + it * 32;
                const uint32_t off = (uint32_t)row * 144 + (uint32_t)cjf * 4;
                cp_async16(dst + off,      gA + (size_t)row * E_DIM + kc + cjf);
                cp_async16(dst + GT + off, gW + (size_t)row * E_DIM + kc + cjf);
            }
        }
        cp_commit();

        // compute on stage kt
        const uint32_t pA = uS + (uint32_t)(kt % 3) * GSTAGE;
        const uint32_t pW = pA + GT;
        #pragma unroll
        for (int kk = 0; kk < 4; kk++) {
            uint32_t Af[4][4];
            #pragma unroll
            for (int mt = 0; mt < 4; mt++)
                ldsm4(Af[mt], pA + (uint32_t)(wm * 64 + mt * 16 + lrow) * 144 + kk * 32 + lk16);
            uint32_t Bf[2][4];
            #pragma unroll
            for (int nb = 0; nb < 2; nb++)
                ldsm4(Bf[nb], pW + (uint32_t)(wn * 32 + nb * 16 + lrow) * 144 + kk * 32 + lk16);
            #pragma unroll
            for (int mt = 0; mt < 4; mt++) {
                #pragma unroll
                for (int nt = 0; nt < 4; nt++) {
                    const int nb = nt >> 1, hf = nt & 1;
                    mma_tf32(acc[mt][nt], Af[mt], Bf[nb][hf], Bf[nb][hf + 2]);
                }
            }
        }
    }

    // ---- epilogue ----
    const int g   = lane >> 2;
    const int tig = lane & 3;
    #pragma unroll
    for (int mt = 0; mt < 4; mt++) {
        #pragma unroll
        for (int nt = 0; nt < 4; nt++) {
            const int m0 = bm + wm * 64 + mt * 16 + g;
            const int n0 = bn + wn * 32 + nt * 8 + tig * 2;
            const float b0 = bz[n0], b1 = bz[n0 + 1];
            float v[4];
            #pragma unroll
            for (int r = 0; r < 4; r++)
                v[r] = (acc[mt][nt][r] + ((r & 1) ? b1 : b0)) * scale;
            if (mode == 1) {
                #pragma unroll
                for (int rr = 0; rr < 2; rr++) {
                    const int m = m0 + rr * 8;
                    const int t = m >> 1;        // B_DIM == 2
                    const int b = m & 1;
                    const int h = n0 >> 6;
                    const int dd = n0 & 63;
                    uint32_t hi, lo;
                    split2(v[rr * 2], v[rr * 2 + 1], hi, lo);
                    const size_t idx = (((size_t)(b * H_DIM + h)) * T_DIM + t) * D_DIM + dd;
                    *reinterpret_cast<uint32_t*>(&Vhb[idx]) = hi;
                    *reinterpret_cast<uint32_t*>(&Vlb[idx]) = lo;
                }
            } else if (mode == 2) {
                #pragma unroll
                for (int rr = 0; rr < 2; rr++) {
                    const int m = m0 + rr * 8;
                    const int t = m >> 1;
                    const int b = m & 1;
                    const int h = n0 >> 6;
                    const int dd = n0 & 63;
                    const size_t idx = (((size_t)(b * H_DIM + h)) * T_DIM + t) * D_DIM + dd;
                    *(float2*)(Cf + idx) = make_float2(to_tf32(v[0 + rr * 2]),
                                                       to_tf32(v[1 + rr * 2]));
                }
            } else {
                #pragma unroll
                for (int r = 0; r < 4; r++) {
                    const int m = m0 + ((r >> 1) << 3);
                    const int n = n0 + (r & 1);
                    Cflat[(size_t)m * E_DIM + n] = v[r];
                }
            }
        }
    }
}

// ---------------------------------------------------------------------------
// MMA flash attention (unchanged, known-good). Block = 64 queries x 1 head.
// QK^T in tf32 (log2e folded into Q), PV in bf16x3, exp2 softmax.
// ---------------------------------------------------------------------------
#define AOFF_Q  0
#define AOFF_K  17408
#define AOFF_VH 34816
#define AOFF_VL 44032
#define ATT_SMEM 53248

__global__ __launch_bounds__(128, 4) void attn_mma(
    const float* __restrict__ Qtf, const float* __restrict__ Ktf,
    const __nv_bfloat16* __restrict__ Vhb, const __nv_bfloat16* __restrict__ Vlb,
    float* __restrict__ ctx)
{
    extern __shared__ __align__(16) char smraw[];

    const int tid  = threadIdx.x;
    const int lane = tid & 31;
    const int w    = tid >> 5;       // 0..3
    const int qt   = blockIdx.x;     // 0..31
    const int hg   = blockIdx.y;     // 0..31 = b*H + h
    const int lrow = lane & 15;
    const int lk16 = ((lane >> 4) & 1) << 4;
    const int rg   = lane >> 2;
    const int tig  = lane & 3;

    const uint32_t uSM = smem_u32(smraw);

    {
        const uint4* gq = (const uint4*)(Qtf + ((size_t)hg * T_DIM + qt * 64) * D_DIM);
        #pragma unroll
        for (int i = 0; i < 8; i++) {
            int c = tid + i * 128;
            int row = c >> 4, j = c & 15;
            *(uint4*)(smraw + AOFF_Q + row * 272 + j * 16) = gq[c];
        }
    }

    float o[8][4];
    #pragma unroll
    for (int nt = 0; nt < 8; nt++)
        #pragma unroll
        for (int r = 0; r < 4; r++) o[nt][r] = 0.f;
    float m0 = -CUDART_INF_F, m1 = -CUDART_INF_F, l0 = 0.f, l1 = 0.f;

    const uint4* gK  = (const uint4*)(Ktf + (size_t)hg * T_DIM * D_DIM);
    const uint4* gVh = (const uint4*)(Vhb + (size_t)hg * T_DIM * D_DIM);
    const uint4* gVl = (const uint4*)(Vlb + (size_t)hg * T_DIM * D_DIM);

    for (int st = 0; st < T_DIM / 64; st++) {
        __syncthreads();
        #pragma unroll
        for (int i = 0; i < 8; i++) {
            int c = tid + i * 128;
            int row = c >> 4, j = c & 15;
            *(uint4*)(smraw + AOFF_K + row * 272 + j * 16) = gK[st * 1024 + c];
        }
        #pragma unroll
        for (int i = 0; i < 4; i++) {
            int c = tid + i * 128;
            int row = c >> 3, j = c & 7;
            int off = row * 144 + j * 16;
            *(uint4*)(smraw + AOFF_VH + off) = gVh[st * 512 + c];
            *(uint4*)(smraw + AOFF_VL + off) = gVl[st * 512 + c];
        }
        __syncthreads();

        float s[8][4];
        #pragma unroll
        for (int nt = 0; nt < 8; nt++)
            #pragma unroll
            for (int r = 0; r < 4; r++) s[nt][r] = 0.f;

        #pragma unroll
        for (int kk = 0; kk < 8; kk++) {
            uint32_t qa[4];
            ldsm4(qa, uSM + AOFF_Q + (uint32_t)(w * 16 + lrow) * 272 + kk * 32 + lk16);
            uint32_t kf[4][4];
            #pragma unroll
            for (int nb = 0; nb < 4; nb++)
                ldsm4(kf[nb], uSM + AOFF_K + (uint32_t)(nb * 16 + lrow) * 272 + kk * 32 + lk16);
            #pragma unroll
            for (int nb = 0; nb < 4; nb++) {
                mma_tf32(s[2 * nb],     qa, kf[nb][0], kf[nb][2]);
                mma_tf32(s[2 * nb + 1], qa, kf[nb][1], kf[nb][3]);
            }
        }

        float mx0 = -CUDART_INF_F, mx1 = -CUDART_INF_F;
        #pragma unroll
        for (int nt = 0; nt < 8; nt++) {
            mx0 = fmaxf(mx0, fmaxf(s[nt][0], s[nt][1]));
            mx1 = fmaxf(mx1, fmaxf(s[nt][2], s[nt][3]));
        }
        mx0 = fmaxf(mx0, __shfl_xor_sync(0xffffffffu, mx0, 1));
        mx0 = fmaxf(mx0, __shfl_xor_sync(0xffffffffu, mx0, 2));
        mx1 = fmaxf(mx1, __shfl_xor_sync(0xffffffffu, mx1, 1));
        mx1 = fmaxf(mx1, __shfl_xor_sync(0xffffffffu, mx1, 2));
        const float mn0 = fmaxf(m0, mx0), mn1 = fmaxf(m1, mx1);
        const float al0 = ex2f(m0 - mn0), al1 = ex2f(m1 - mn1);
        m0 = mn0; m1 = mn1;
        float sum0 = 0.f, sum1 = 0.f;
        #pragma unroll
        for (int nt = 0; nt < 8; nt++) {
            s[nt][0] = ex2f(s[nt][0] - m0);
            s[nt][1] = ex2f(s[nt][1] - m0);
            s[nt][2] = ex2f(s[nt][2] - m1);
            s[nt][3] = ex2f(s[nt][3] - m1);
            sum0 += s[nt][0] + s[nt][1];
            sum1 += s[nt][2] + s[nt][3];
        }
        sum0 += __shfl_xor_sync(0xffffffffu, sum0, 1);
        sum0 += __shfl_xor_sync(0xffffffffu, sum0, 2);
        sum1 += __shfl_xor_sync(0xffffffffu, sum1, 1);
        sum1 += __shfl_xor_sync(0xffffffffu, sum1, 2);
        l0 = l0 * al0 + sum0;
        l1 = l1 * al1 + sum1;
        #pragma unroll
        for (int nt = 0; nt < 8; nt++) {
            o[nt][0] *= al0; o[nt][1] *= al0;
            o[nt][2] *= al1; o[nt][3] *= al1;
        }

        uint32_t AH[4][4], AL[4][4];
        #pragma unroll
        for (int kb = 0; kb < 4; kb++) {
            const int t0 = 2 * kb, t1 = 2 * kb + 1;
            split2(s[t0][0], s[t0][1], AH[kb][0], AL[kb][0]);
            split2(s[t0][2], s[t0][3], AH[kb][1], AL[kb][1]);
            split2(s[t1][0], s[t1][1], AH[kb][2], AL[kb][2]);
            split2(s[t1][2], s[t1][3], AH[kb][3], AL[kb][3]);
        }

        #pragma unroll
        for (int kb = 0; kb < 4; kb++) {
            uint32_t vh[4][4], vl[4][4];
            #pragma unroll
            for (int db = 0; db < 4; db++) {
                const uint32_t a = uSM + AOFF_VH + (uint32_t)(kb * 16 + lrow) * 144 + db * 32 + lk16;
                ldsm4t(vh[db], a);
                ldsm4t(vl[db], a + (AOFF_VL - AOFF_VH));
            }
            #pragma unroll
            for (int db = 0; db < 4; db++) {
                #pragma unroll
                for (int hs = 0; hs < 2; hs++) {
                    const int nt = db * 2 + hs;
                    const uint32_t b0h = vh[db][hs * 2], b1h = vh[db][hs * 2 + 1];
                    mma_bf16(o[nt], AH[kb], b0h, b1h);
                    mma_bf16(o[nt], AL[kb], b0h, b1h);
                    mma_bf16(o[nt], AH[kb], vl[db][hs * 2], vl[db][hs * 2 + 1]);
                }
            }
        }
    }

    const float inv0 = 1.f / l0, inv1 = 1.f / l1;
    const int bb = hg >> 4;
    const int hh = hg & 15;
    const int q0 = qt * 64 + w * 16 + rg;
    #pragma unroll
    for (int nt = 0; nt < 8; nt++) {
        const int d = hh * 64 + nt * 8 + tig * 2;
        *(float2*)(ctx + ((size_t)q0 * B_DIM + bb) * E_DIM + d) =
            make_float2(o[nt][0] * inv0, o[nt][1] * inv0);
        *(float2*)(ctx + ((size_t)(q0 + 8) * B_DIM + bb) * E_DIM + d) =
            make_float2(o[nt][2] * inv1, o[nt][3] * inv1);
    }
}

// ---------------------------------------------------------------------------
extern "C" void kernel_launch(void* const* d_in, const int* in_sizes, int n_in,
                              void* d_out, int out_size)
{
    const float* query = (const float*)d_in[0];
    const float* key   = (const float*)d_in[1];
    const float* value = (const float*)d_in[2];
    const float* Win   = (const float*)d_in[3];   // (3E, E)
    const float* bin   = (const float*)d_in[4];   // (3E,)
    const float* Wout  = (const float*)d_in[5];   // (E, E)
    const float* bout  = (const float*)d_in[6];   // (E,)
    float* out = (float*)d_out;

    float *Qtf, *Ktf, *ctx;
    __nv_bfloat16 *Vhb, *Vlb;
    cudaGetSymbolAddress((void**)&Qtf, g_Qtf);
    cudaGetSymbolAddress((void**)&Ktf, g_Ktf);
    cudaGetSymbolAddress((void**)&Vhb, g_Vhb);
    cudaGetSymbolAddress((void**)&Vlb, g_Vlb);
    cudaGetSymbolAddress((void**)&ctx, g_ctx);

    const float scaleQ = 0.125f * 1.44269504089f;   // 1/sqrt(64) * log2(e)

    cudaFuncSetAttribute(gemm_tf32, cudaFuncAttributeMaxDynamicSharedMemorySize, GSMEM);
    cudaFuncSetAttribute(attn_mma,  cudaFuncAttributeMaxDynamicSharedMemorySize, ATT_SMEM);

    // QKV projections, batched over grid.z
    gemm_tf32<<<dim3(E_DIM / 128, NROWS / 128, 3), 256, GSMEM>>>(
        query, key, value, Win, bin, Qtf, Ktf, Vhb, Vlb, nullptr, scaleQ, 1);

    attn_mma<<<dim3(T_DIM / 64, NHEADS), 128, ATT_SMEM>>>(Qtf, Ktf, Vhb, Vlb, ctx);

    // out projection (flat fp32)
    gemm_tf32<<<dim3(E_DIM / 128, NROWS / 128, 1), 256, GSMEM>>>(
        ctx, nullptr, nullptr, Wout, bout, nullptr, nullptr, nullptr, nullptr, out, 1.f, 0);
}